// round 7
// baseline (speedup 1.0000x reference)
#include <cuda_runtime.h>
#include <cuda_bf16.h>
#include <math.h>
#include <stdint.h>

#define NSUP 65536
#define EDIM 512
#define CCLS 64
#define HEADS 8
#define DHEAD 64
#define LVLS 3
#define SLOT 2048
#define NPART 8

// ---------------- scratch (device globals; no allocation) ----------------
__device__ float g_t[(size_t)NSUP * EDIM];
__device__ float g_feat[(size_t)CCLS * SLOT * EDIM];
__device__ float g_mu[NSUP];
__device__ float g_rstd[NSUP];
__device__ int   g_pos[NSUP];
__device__ int   g_count[CCLS];
__device__ float g_proto[(size_t)LVLS * CCLS * EDIM];
__device__ float g_lns[2][NSUP];
__device__ float g_lnq[2][NSUP];
__device__ float g_ctx[CCLS * EDIM];
__device__ float g_uvec[CCLS * HEADS * EDIM];
__device__ float g_pm[CCLS * NPART * HEADS];
__device__ float g_pl[CCLS * NPART * HEADS];
__device__ float g_pacc[(size_t)CCLS * NPART * HEADS * EDIM];
__device__ __nv_bfloat16 g_xhi[(size_t)NSUP * EDIM];
__device__ __nv_bfloat16 g_xlo[(size_t)NSUP * EDIM];
__device__ __nv_bfloat16 g_ahi[(size_t)NSUP * EDIM];
__device__ __nv_bfloat16 g_alo[(size_t)NSUP * EDIM];
__device__ __nv_bfloat16 g_wh[(size_t)6 * EDIM * EDIM];   // W^T splits: [mat][n][k]
__device__ __nv_bfloat16 g_wl[(size_t)6 * EDIM * EDIM];

// ---------------- PTX helpers ----------------
__device__ __forceinline__ uint32_t smem_u32(const void* p) {
    uint32_t a;
    asm("{ .reg .u64 t; cvta.to.shared.u64 t, %1; cvt.u32.u64 %0, t; }" : "=r"(a) : "l"(p));
    return a;
}
__device__ __forceinline__ void cpa16(uint32_t s, const void* g) {
    asm volatile("cp.async.cg.shared.global [%0], [%1], 16;" :: "r"(s), "l"(g));
}
__device__ __forceinline__ void cpa_commit() { asm volatile("cp.async.commit_group;" ::: "memory"); }
template<int N>
__device__ __forceinline__ void cpa_wait() { asm volatile("cp.async.wait_group %0;" :: "n"(N) : "memory"); }
__device__ __forceinline__ void ldmx4(uint32_t* r, uint32_t a) {
    asm volatile("ldmatrix.sync.aligned.m8n8.x4.shared.b16 {%0,%1,%2,%3}, [%4];"
        : "=r"(r[0]), "=r"(r[1]), "=r"(r[2]), "=r"(r[3]) : "r"(a));
}
__device__ __forceinline__ void mma16816(float* c, const uint32_t* a, uint32_t b0, uint32_t b1) {
    asm volatile("mma.sync.aligned.m16n8k16.row.col.f32.bf16.bf16.f32 "
        "{%0,%1,%2,%3}, {%4,%5,%6,%7}, {%8,%9}, {%0,%1,%2,%3};"
        : "+f"(c[0]), "+f"(c[1]), "+f"(c[2]), "+f"(c[3])
        : "r"(a[0]), "r"(a[1]), "r"(a[2]), "r"(a[3]), "r"(b0), "r"(b1));
}

// ---------------- build class membership ----------------
__global__ void __launch_bounds__(256) build_k(const int* __restrict__ labels) {
    __shared__ int warp_cnt[8];
    __shared__ int s_base;
    int tid = threadIdx.x, lane = tid & 31, w = tid >> 5;
    int c = blockIdx.x;
    if (tid == 0) s_base = 0;
    __syncthreads();
    for (int base = 0; base < NSUP; base += 256) {
        int n = base + tid;
        bool f = (labels[n] == c);
        unsigned m = __ballot_sync(0xffffffffu, f);
        if (lane == 0) warp_cnt[w] = __popc(m);
        __syncthreads();
        int woff = 0, tot = 0;
        #pragma unroll
        for (int i = 0; i < 8; i++) { int v = warp_cnt[i]; if (i < w) woff += v; tot += v; }
        if (f) g_pos[n] = c * SLOT + s_base + woff + __popc(m & ((1u << lane) - 1u));
        __syncthreads();
        if (tid == 0) s_base += tot;
        __syncthreads();
    }
    if (tid == 0) g_count[c] = s_base;
}

// ---------------- bf16 splits ----------------
__global__ void __launch_bounds__(256) xsplit_k(const float* __restrict__ X) {
    size_t i = (size_t)blockIdx.x * 256 + threadIdx.x;   // float4 index
    float4 v = ((const float4*)X)[i];
    __nv_bfloat16 h0 = __float2bfloat16(v.x), h1 = __float2bfloat16(v.y);
    __nv_bfloat16 h2 = __float2bfloat16(v.z), h3 = __float2bfloat16(v.w);
    __nv_bfloat16 l0 = __float2bfloat16(v.x - __bfloat162float(h0));
    __nv_bfloat16 l1 = __float2bfloat16(v.y - __bfloat162float(h1));
    __nv_bfloat16 l2 = __float2bfloat16(v.z - __bfloat162float(h2));
    __nv_bfloat16 l3 = __float2bfloat16(v.w - __bfloat162float(h3));
    uint2 ph, pl;
    ph.x = (uint32_t)__bfloat16_as_ushort(h0) | ((uint32_t)__bfloat16_as_ushort(h1) << 16);
    ph.y = (uint32_t)__bfloat16_as_ushort(h2) | ((uint32_t)__bfloat16_as_ushort(h3) << 16);
    pl.x = (uint32_t)__bfloat16_as_ushort(l0) | ((uint32_t)__bfloat16_as_ushort(l1) << 16);
    pl.y = (uint32_t)__bfloat16_as_ushort(l2) | ((uint32_t)__bfloat16_as_ushort(l3) << 16);
    ((uint2*)g_xhi)[i] = ph;
    ((uint2*)g_xlo)[i] = pl;
}

__global__ void __launch_bounds__(256) wsplit_k(const float* __restrict__ W1, const float* __restrict__ W2) {
    int m = blockIdx.y;            // 0..5
    int idx = blockIdx.x * 256 + threadIdx.x;   // < 512*512
    int k = idx >> 9, n = idx & 511;
    const float* src = (m < 3) ? (W1 + (size_t)m * EDIM * EDIM) : (W2 + (size_t)(m - 3) * EDIM * EDIM);
    float v = src[(size_t)k * EDIM + n];
    __nv_bfloat16 h = __float2bfloat16(v);
    __nv_bfloat16 l = __float2bfloat16(v - __bfloat162float(h));
    size_t dst = (size_t)m * EDIM * EDIM + (size_t)n * EDIM + k;   // transpose
    g_wh[dst] = h;
    g_wl[dst] = l;
}

// ---------------- LN stats from partials ----------------
__global__ void __launch_bounds__(256) ln2_k() {
    int row = blockIdx.x * 256 + threadIdx.x;
    float s = g_lns[0][row] + g_lns[1][row];
    float q = g_lnq[0][row] + g_lnq[1][row];
    float mu = s * (1.f / EDIM);
    float var = q * (1.f / EDIM) - mu * mu;
    g_mu[row] = mu;
    g_rstd[row] = rsqrtf(var + 1e-5f);
}

// ---------------- LN + ReLU + bf16 split of activations ----------------
__global__ void __launch_bounds__(256) actsplit_k(const float* __restrict__ gamma, const float* __restrict__ beta) {
    size_t i = (size_t)blockIdx.x * 256 + threadIdx.x;   // float4 index
    float4 v = ((const float4*)g_t)[i];
    int row = (int)(i >> 7);
    int col = ((int)i & 127) * 4;
    float mu = g_mu[row], rs = g_rstd[row];
    float4 gg = *(const float4*)(gamma + col);
    float4 bb = *(const float4*)(beta + col);
    float a0 = fmaxf(fmaf((v.x - mu) * rs, gg.x, bb.x), 0.f);
    float a1 = fmaxf(fmaf((v.y - mu) * rs, gg.y, bb.y), 0.f);
    float a2 = fmaxf(fmaf((v.z - mu) * rs, gg.z, bb.z), 0.f);
    float a3 = fmaxf(fmaf((v.w - mu) * rs, gg.w, bb.w), 0.f);
    __nv_bfloat16 h0 = __float2bfloat16(a0), h1 = __float2bfloat16(a1);
    __nv_bfloat16 h2 = __float2bfloat16(a2), h3 = __float2bfloat16(a3);
    __nv_bfloat16 l0 = __float2bfloat16(a0 - __bfloat162float(h0));
    __nv_bfloat16 l1 = __float2bfloat16(a1 - __bfloat162float(h1));
    __nv_bfloat16 l2 = __float2bfloat16(a2 - __bfloat162float(h2));
    __nv_bfloat16 l3 = __float2bfloat16(a3 - __bfloat162float(h3));
    uint2 ph, pl;
    ph.x = (uint32_t)__bfloat16_as_ushort(h0) | ((uint32_t)__bfloat16_as_ushort(h1) << 16);
    ph.y = (uint32_t)__bfloat16_as_ushort(h2) | ((uint32_t)__bfloat16_as_ushort(h3) << 16);
    pl.x = (uint32_t)__bfloat16_as_ushort(l0) | ((uint32_t)__bfloat16_as_ushort(l1) << 16);
    pl.y = (uint32_t)__bfloat16_as_ushort(l2) | ((uint32_t)__bfloat16_as_ushort(l3) << 16);
    ((uint2*)g_ahi)[i] = ph;
    ((uint2*)g_alo)[i] = pl;
}

// ---------------- mma.sync GEMM: C[65536x512] = A @ W   (bf16 hi/lo 3-pass, fp32 accum) ----------------
// CTA tile 128x256, 512 threads, 16 warps (4x4), warp tile 32x64, K-chunk 32, cp.async double buffer.
#define GM_NCH 16
#define GM_STRB 80                          // padded row stride in bytes (40 bf16)
#define GM_AH 0
#define GM_AL (128 * GM_STRB)               // 10240
#define GM_BH (2 * 128 * GM_STRB)           // 20480
#define GM_BL (GM_BH + 256 * GM_STRB)       // 40960
#define GM_BUF (GM_BL + 256 * GM_STRB)      // 61440 per buffer
#define GM_SMEM (2 * GM_BUF)                // 122880 B

template<int EPI>
__global__ void __launch_bounds__(512, 1) gemm_mma_k(
    const __nv_bfloat16* __restrict__ Ahi, const __nv_bfloat16* __restrict__ Alo,
    const __nv_bfloat16* __restrict__ Bhi, const __nv_bfloat16* __restrict__ Blo,
    const float* __restrict__ bias, float* __restrict__ Cout)
{
    extern __shared__ char smem[];
    uint32_t sb = smem_u32(smem);
    int tid = threadIdx.x, lane = tid & 31, wid = tid >> 5;
    int wm = wid >> 2, wn = wid & 3;      // 4 x 4 warp grid; warp tile 32x64
    int row0 = blockIdx.x * 128, col0 = blockIdx.y * 256;

    float acc[2][8][4];                   // [mb][nb*2+half][frag]
    #pragma unroll
    for (int i = 0; i < 2; i++)
        #pragma unroll
        for (int j = 0; j < 8; j++)
            #pragma unroll
            for (int t = 0; t < 4; t++) acc[i][j][t] = 0.f;

    // per-warp ldmatrix base offsets (constant all loop long)
    int lr = lane & 15, lc = lane >> 4;
    uint32_t a_off = (uint32_t)((wm * 32 + lr) * GM_STRB + lc * 16);
    uint32_t b_off = (uint32_t)(GM_BH + (wn * 64 + lr) * GM_STRB + lc * 16);

    // load mapping
    int lrow = tid >> 2, lseg = tid & 3;
    auto load_chunk = [&](int ch) {
        int b = ch & 1;
        uint32_t s0 = sb + b * GM_BUF;
        int k0 = ch * 32;
        {   // A: 128 rows x 4 segs = 512 units
            uint32_t so = (uint32_t)(lrow * GM_STRB + lseg * 16);
            size_t ga = (size_t)(row0 + lrow) * EDIM + k0 + lseg * 8;
            cpa16(s0 + GM_AH + so, Ahi + ga);
            cpa16(s0 + GM_AL + so, Alo + ga);
        }
        #pragma unroll
        for (int it = 0; it < 2; it++) {   // B: 256 rows x 4 segs = 1024 units
            int u = tid + it * 512;
            int r = u >> 2, sg = u & 3;
            uint32_t so = (uint32_t)(r * GM_STRB + sg * 16);
            size_t gb = (size_t)(col0 + r) * EDIM + k0 + sg * 8;
            cpa16(s0 + GM_BH + so, Bhi + gb);
            cpa16(s0 + GM_BL + so, Blo + gb);
        }
        cpa_commit();
    };

    load_chunk(0);
    load_chunk(1);

    for (int ch = 0; ch < GM_NCH; ch++) {
        if (ch == GM_NCH - 1) cpa_wait<0>(); else cpa_wait<1>();
        __syncthreads();
        uint32_t s0 = sb + (ch & 1) * GM_BUF;
        #pragma unroll
        for (int ks = 0; ks < 2; ks++) {
            uint32_t ah[2][4], al[2][4];
            #pragma unroll
            for (int mb = 0; mb < 2; mb++) {
                uint32_t ra = s0 + a_off + (uint32_t)(mb * 16 * GM_STRB + ks * 32);
                ldmx4(ah[mb], ra);
                ldmx4(al[mb], ra + GM_AL);
            }
            #pragma unroll
            for (int nb = 0; nb < 4; nb++) {
                uint32_t rb = s0 + b_off + (uint32_t)(nb * 16 * GM_STRB + ks * 32);
                uint32_t bh[4], bl[4];
                ldmx4(bh, rb);
                ldmx4(bl, rb + (GM_BL - GM_BH));
                #pragma unroll
                for (int mb = 0; mb < 2; mb++) {
                    mma16816(acc[mb][nb * 2],     ah[mb], bh[0], bh[2]);
                    mma16816(acc[mb][nb * 2],     al[mb], bh[0], bh[2]);
                    mma16816(acc[mb][nb * 2],     ah[mb], bl[0], bl[2]);
                    mma16816(acc[mb][nb * 2 + 1], ah[mb], bh[1], bh[3]);
                    mma16816(acc[mb][nb * 2 + 1], al[mb], bh[1], bh[3]);
                    mma16816(acc[mb][nb * 2 + 1], ah[mb], bl[1], bl[3]);
                }
            }
        }
        __syncthreads();
        if (ch + 2 < GM_NCH) load_chunk(ch + 2);
    }

    // epilogue: bias add; EPI0: dense rows + LN partial sums; EPI1: scatter via g_pos
    float* s_sum = (float*)smem;            // 128*4 floats (dead buffer 0 region)
    float* s_sq  = (float*)(smem + 2048);
    #pragma unroll
    for (int mb = 0; mb < 2; mb++) {
        int rl = wm * 32 + mb * 16 + (lane >> 2);
        size_t dr0, dr1;
        if (EPI == 0) { dr0 = (size_t)(row0 + rl); dr1 = (size_t)(row0 + rl + 8); }
        else          { dr0 = (size_t)g_pos[row0 + rl]; dr1 = (size_t)g_pos[row0 + rl + 8]; }
        float* d0 = Cout + dr0 * EDIM;
        float* d1 = Cout + dr1 * EDIM;
        float rs0 = 0.f, rq0 = 0.f, rs1 = 0.f, rq1 = 0.f;
        #pragma unroll
        for (int j = 0; j < 8; j++) {
            int col = col0 + wn * 64 + (j >> 1) * 16 + (j & 1) * 8 + (lane & 3) * 2;
            float2 bb = *(const float2*)(bias + col);
            float2 o0, o1;
            o0.x = acc[mb][j][0] + bb.x; o0.y = acc[mb][j][1] + bb.y;
            o1.x = acc[mb][j][2] + bb.x; o1.y = acc[mb][j][3] + bb.y;
            *(float2*)(d0 + col) = o0;
            *(float2*)(d1 + col) = o1;
            if (EPI == 0) {
                rs0 += o0.x + o0.y; rq0 += o0.x * o0.x + o0.y * o0.y;
                rs1 += o1.x + o1.y; rq1 += o1.x * o1.x + o1.y * o1.y;
            }
        }
        if (EPI == 0) {
            rs0 += __shfl_xor_sync(0xffffffffu, rs0, 1); rs0 += __shfl_xor_sync(0xffffffffu, rs0, 2);
            rq0 += __shfl_xor_sync(0xffffffffu, rq0, 1); rq0 += __shfl_xor_sync(0xffffffffu, rq0, 2);
            rs1 += __shfl_xor_sync(0xffffffffu, rs1, 1); rs1 += __shfl_xor_sync(0xffffffffu, rs1, 2);
            rq1 += __shfl_xor_sync(0xffffffffu, rq1, 1); rq1 += __shfl_xor_sync(0xffffffffu, rq1, 2);
            if ((lane & 3) == 0) {
                s_sum[rl * 4 + wn] = rs0;       s_sq[rl * 4 + wn] = rq0;
                s_sum[(rl + 8) * 4 + wn] = rs1; s_sq[(rl + 8) * 4 + wn] = rq1;
            }
        }
    }
    if (EPI == 0) {
        __syncthreads();
        if (tid < 128) {
            float s = s_sum[tid * 4] + s_sum[tid * 4 + 1] + s_sum[tid * 4 + 2] + s_sum[tid * 4 + 3];
            float q = s_sq[tid * 4] + s_sq[tid * 4 + 1] + s_sq[tid * 4 + 2] + s_sq[tid * 4 + 3];
            g_lns[blockIdx.y][row0 + tid] = s;
            g_lnq[blockIdx.y][row0 + tid] = q;
        }
    }
}

// ---------------- attention part 1: per-class column means ----------------
__global__ void __launch_bounds__(256) colsum_k() {
    __shared__ float red[256];
    int tid = threadIdx.x;
    int c = blockIdx.x, col0 = blockIdx.y * 128;
    int M = g_count[c];
    const float* fbase = g_feat + (size_t)c * SLOT * EDIM;
    int half = tid >> 7, colx = tid & 127;
    float s = 0.f;
    for (int i = half; i < M; i += 2) s += fbase[(size_t)i * EDIM + col0 + colx];
    red[tid] = s;
    __syncthreads();
    if (tid < 128) g_ctx[c * EDIM + col0 + tid] = (red[tid] + red[tid + 128]) / (float)M;
}

// ---------------- attention part 2: q then projected u vectors ----------------
__global__ void __launch_bounds__(256) qu_k(const float* __restrict__ Wq, const float* __restrict__ bq,
                                            const float* __restrict__ Wk) {
    __shared__ float CTX[512];
    __shared__ float Q[512];
    int tid = threadIdx.x;
    int c = blockIdx.x;
    CTX[tid] = g_ctx[c * EDIM + tid];
    CTX[tid + 256] = g_ctx[c * EDIM + tid + 256];
    __syncthreads();
    {
        float q0 = bq[tid], q1 = bq[tid + 256];
        for (int k = 0; k < EDIM; k++) {
            float cv = CTX[k];
            q0 = fmaf(cv, Wq[(size_t)k * EDIM + tid], q0);
            q1 = fmaf(cv, Wq[(size_t)k * EDIM + tid + 256], q1);
        }
        Q[tid] = q0; Q[tid + 256] = q1;
    }
    __syncthreads();
    // u_h = scale * Wk[:, h-block] @ q_h (bk dropped: softmax shift invariance)
    for (int idx = tid; idx < HEADS * EDIM; idx += 256) {
        int h = idx >> 9, e = idx & 511;
        const float* wk = Wk + (size_t)e * EDIM + h * DHEAD;
        const float* qh = Q + h * DHEAD;
        float s = 0.f;
        #pragma unroll 8
        for (int d = 0; d < DHEAD; d++) s = fmaf(wk[d], qh[d], s);
        g_uvec[c * HEADS * EDIM + idx] = s * 0.125f;
    }
}

// ---------------- attention part 3: partial online softmax (grid CCLS x NPART) ----------------
#define AP_SMEM ((4096 + 2 * 8192) * 4)   // U + FS double buffer = 81920 B

__global__ void __launch_bounds__(256) attn_part_k() {
    extern __shared__ float sm[];
    float* U  = sm;          // 8*512
    float* FS = sm + 4096;   // 2*16*512

    int tid = threadIdx.x, lane = tid & 31, w = tid >> 5;
    int c = blockIdx.x, p = blockIdx.y;
    int M = g_count[c];
    const float* fbase = g_feat + (size_t)c * SLOT * EDIM;

    for (int i = tid; i < 1024; i += 256)
        ((float4*)U)[i] = ((const float4*)(g_uvec + (size_t)c * HEADS * EDIM))[i];
    __syncthreads();

    float u4r[16], acc_r[16];
    {
        const float4* U4 = (const float4*)(U + w * EDIM);
        #pragma unroll
        for (int q = 0; q < 4; q++) {
            float4 uu = U4[lane + 32 * q];
            u4r[4*q+0] = uu.x; u4r[4*q+1] = uu.y; u4r[4*q+2] = uu.z; u4r[4*q+3] = uu.w;
            acc_r[4*q+0] = 0.f; acc_r[4*q+1] = 0.f; acc_r[4*q+2] = 0.f; acc_r[4*q+3] = 0.f;
        }
    }
    float mmax = -3.0e38f, lsum = 0.f;

    int nch = (M + 15) >> 4;
    auto load_chunk = [&](int ch, int bsel) {
        int rbase = ch * 16;
        #pragma unroll
        for (int jj = 0; jj < 8; jj++) {
            int vid = tid + jj * 256;
            int r = vid >> 7;
            int c4 = vid & 127;
            if (rbase + r < M) {
                float4 v = *(const float4*)(fbase + (size_t)(rbase + r) * EDIM + c4 * 4);
                *(float4*)(FS + bsel * 8192 + r * 512 + c4 * 4) = v;
            }
        }
    };
    if (p < nch) load_chunk(p, 0);
    __syncthreads();
    int it = 0;
    for (int ch = p; ch < nch; ch += NPART, it ^= 1) {
        if (ch + NPART < nch) load_chunk(ch + NPART, it ^ 1);
        int rem = M - ch * 16; if (rem > 16) rem = 16;
        float* fsb = FS + it * 8192;
        float sv[16];
        #pragma unroll
        for (int i = 0; i < 16; i++) {
            if (i < rem) {
                const float4* fr = (const float4*)(fsb + i * 512);
                float d = 0.f;
                #pragma unroll
                for (int q = 0; q < 4; q++) {
                    float4 f = fr[lane + 32 * q];
                    d = fmaf(f.x, u4r[4*q+0], d);
                    d = fmaf(f.y, u4r[4*q+1], d);
                    d = fmaf(f.z, u4r[4*q+2], d);
                    d = fmaf(f.w, u4r[4*q+3], d);
                }
                #pragma unroll
                for (int o = 16; o > 0; o >>= 1) d += __shfl_xor_sync(0xffffffffu, d, o);
                sv[i] = d;
            } else sv[i] = -3.0e38f;
        }
        float m_c = sv[0];
        #pragma unroll
        for (int i = 1; i < 16; i++) m_c = fmaxf(m_c, sv[i]);
        float newmax = fmaxf(mmax, m_c);
        float fac = __expf(mmax - newmax);
        lsum *= fac;
        #pragma unroll
        for (int j = 0; j < 16; j++) acc_r[j] *= fac;
        #pragma unroll
        for (int i = 0; i < 16; i++) {
            if (i < rem) {
                float pex = __expf(sv[i] - newmax);
                lsum += pex;
                const float4* fr = (const float4*)(fsb + i * 512);
                #pragma unroll
                for (int q = 0; q < 4; q++) {
                    float4 f = fr[lane + 32 * q];
                    acc_r[4*q+0] = fmaf(pex, f.x, acc_r[4*q+0]);
                    acc_r[4*q+1] = fmaf(pex, f.y, acc_r[4*q+1]);
                    acc_r[4*q+2] = fmaf(pex, f.z, acc_r[4*q+2]);
                    acc_r[4*q+3] = fmaf(pex, f.w, acc_r[4*q+3]);
                }
            }
        }
        mmax = newmax;
        __syncthreads();
    }
    size_t base = (size_t)(c * NPART + p) * HEADS + w;
    if (lane == 0) { g_pm[base] = mmax; g_pl[base] = lsum; }
    float4* P4 = (float4*)(g_pacc + base * EDIM);
    #pragma unroll
    for (int q = 0; q < 4; q++) {
        float4 o;
        o.x = acc_r[4*q+0]; o.y = acc_r[4*q+1]; o.z = acc_r[4*q+2]; o.w = acc_r[4*q+3];
        P4[lane + 32 * q] = o;
    }
}

// ---------------- attention part 4: merge partials + Wv + Wo ----------------
__global__ void __launch_bounds__(256) merge_k(const float* __restrict__ Wv, const float* __restrict__ bv,
                                               const float* __restrict__ Wo, const float* __restrict__ bo,
                                               int level) {
    __shared__ float ACCA[HEADS * EDIM];
    __shared__ float OUTS[EDIM];
    int tid = threadIdx.x, lane = tid & 31, w = tid >> 5;
    int c = blockIdx.x;

    // warp w merges head w
    {
        float mp[NPART], lp[NPART];
        float gm = -3.0e38f;
        #pragma unroll
        for (int p = 0; p < NPART; p++) {
            size_t b = (size_t)(c * NPART + p) * HEADS + w;
            mp[p] = g_pm[b]; lp[p] = g_pl[b];
            gm = fmaxf(gm, mp[p]);
        }
        float coef[NPART];
        float L = 0.f;
        #pragma unroll
        for (int p = 0; p < NPART; p++) { coef[p] = __expf(mp[p] - gm); L += lp[p] * coef[p]; }
        float invL = 1.f / L;
        #pragma unroll
        for (int q = 0; q < 4; q++) {
            int e4 = lane + 32 * q;
            float4 s = make_float4(0.f, 0.f, 0.f, 0.f);
            #pragma unroll
            for (int p = 0; p < NPART; p++) {
                size_t b = (size_t)(c * NPART + p) * HEADS + w;
                float4 v = ((const float4*)(g_pacc + b * EDIM))[e4];
                s.x = fmaf(coef[p], v.x, s.x); s.y = fmaf(coef[p], v.y, s.y);
                s.z = fmaf(coef[p], v.z, s.z); s.w = fmaf(coef[p], v.w, s.w);
            }
            float4 o;
            o.x = s.x * invL; o.y = s.y * invL; o.z = s.z * invL; o.w = s.w * invL;
            ((float4*)(ACCA + w * EDIM))[e4] = o;
        }
    }
    __syncthreads();

    // out = concat_h[(attn-weighted feat) @ Wv_h] + bv
    {
        int o0 = tid, o1 = tid + 256;
        int h0 = o0 >> 6, h1 = o1 >> 6;
        float a0 = bv[o0], a1 = bv[o1];
        for (int e = 0; e < EDIM; e++) {
            a0 = fmaf(ACCA[h0 * EDIM + e], Wv[(size_t)e * EDIM + o0], a0);
            a1 = fmaf(ACCA[h1 * EDIM + e], Wv[(size_t)e * EDIM + o1], a1);
        }
        OUTS[o0] = a0; OUTS[o1] = a1;
    }
    __syncthreads();

    // proto = out @ Wo + bo
    {
        int o0 = tid, o1 = tid + 256;
        float p0 = bo[o0], p1 = bo[o1];
        for (int e = 0; e < EDIM; e++) {
            float ov = OUTS[e];
            p0 = fmaf(ov, Wo[(size_t)e * EDIM + o0], p0);
            p1 = fmaf(ov, Wo[(size_t)e * EDIM + o1], p1);
        }
        size_t pb = ((size_t)level * CCLS + c) * EDIM;
        g_proto[pb + o0] = p0;
        g_proto[pb + o1] = p1;
    }
}

// ---------------- final combine ----------------
__global__ void __launch_bounds__(256) combine_k(const float* __restrict__ lw,
                                                 const float* __restrict__ lt,
                                                 float* __restrict__ out) {
    int idx = blockIdx.x * 256 + threadIdx.x;
    float a0 = lw[0], a1 = lw[1], a2 = lw[2];
    float mx = fmaxf(a0, fmaxf(a1, a2));
    float e0 = expf(a0 - mx), e1 = expf(a1 - mx), e2 = expf(a2 - mx);
    float inv = 1.f / (e0 + e1 + e2);
    float w0 = e0 * inv / lt[0], w1 = e1 * inv / lt[1], w2 = e2 * inv / lt[2];
    out[idx] = g_proto[idx] * w0
             + g_proto[(size_t)CCLS * EDIM + idx] * w1
             + g_proto[(size_t)2 * CCLS * EDIM + idx] * w2;
}

// ---------------- launch ----------------
extern "C" void kernel_launch(void* const* d_in, const int* in_sizes, int n_in,
                              void* d_out, int out_size) {
    (void)in_sizes; (void)n_in; (void)out_size;
    const float* X      = (const float*)d_in[0];
    const int*   labels = (const int*)d_in[1];
    const float* W1     = (const float*)d_in[2];
    const float* b1     = (const float*)d_in[3];
    const float* gamma  = (const float*)d_in[4];
    const float* beta   = (const float*)d_in[5];
    const float* W2     = (const float*)d_in[6];
    const float* b2     = (const float*)d_in[7];
    const float* Wq     = (const float*)d_in[8];
    const float* bq     = (const float*)d_in[9];
    const float* Wk     = (const float*)d_in[10];
    const float* Wv     = (const float*)d_in[12];
    const float* bv     = (const float*)d_in[13];
    const float* Wo     = (const float*)d_in[14];
    const float* bo     = (const float*)d_in[15];
    const float* lw     = (const float*)d_in[16];
    const float* lt     = (const float*)d_in[17];
    float* out = (float*)d_out;

    cudaFuncSetAttribute((const void*)gemm_mma_k<0>, cudaFuncAttributeMaxDynamicSharedMemorySize, GM_SMEM);
    cudaFuncSetAttribute((const void*)gemm_mma_k<1>, cudaFuncAttributeMaxDynamicSharedMemorySize, GM_SMEM);
    cudaFuncSetAttribute((const void*)attn_part_k, cudaFuncAttributeMaxDynamicSharedMemorySize, AP_SMEM);

    __nv_bfloat16 *pxhi, *pxlo, *pahi, *palo, *pwh, *pwl;
    float *pt, *pfeat;
    cudaGetSymbolAddress((void**)&pxhi, g_xhi);
    cudaGetSymbolAddress((void**)&pxlo, g_xlo);
    cudaGetSymbolAddress((void**)&pahi, g_ahi);
    cudaGetSymbolAddress((void**)&palo, g_alo);
    cudaGetSymbolAddress((void**)&pwh, g_wh);
    cudaGetSymbolAddress((void**)&pwl, g_wl);
    cudaGetSymbolAddress((void**)&pt, g_t);
    cudaGetSymbolAddress((void**)&pfeat, g_feat);

    build_k<<<64, 256>>>(labels);
    xsplit_k<<<(NSUP * EDIM / 4) / 256, 256>>>(X);
    wsplit_k<<<dim3(1024, 6), 256>>>(W1, W2);

    for (int l = 0; l < LVLS; l++) {
        const __nv_bfloat16* w1h = pwh + (size_t)l * EDIM * EDIM;
        const __nv_bfloat16* w1l = pwl + (size_t)l * EDIM * EDIM;
        const __nv_bfloat16* w2h = pwh + (size_t)(3 + l) * EDIM * EDIM;
        const __nv_bfloat16* w2l = pwl + (size_t)(3 + l) * EDIM * EDIM;
        gemm_mma_k<0><<<dim3(512, 2), 512, GM_SMEM>>>(pxhi, pxlo, w1h, w1l, b1 + l * EDIM, pt);
        ln2_k<<<256, 256>>>();
        actsplit_k<<<(NSUP * EDIM / 4) / 256, 256>>>(gamma + l * EDIM, beta + l * EDIM);
        gemm_mma_k<1><<<dim3(512, 2), 512, GM_SMEM>>>(pahi, palo, w2h, w2l, b2 + l * EDIM, pfeat);
        colsum_k<<<dim3(CCLS, 4), 256>>>();
        qu_k<<<CCLS, 256>>>(Wq, bq, Wk);
        attn_part_k<<<dim3(CCLS, NPART), 256, AP_SMEM>>>();
        merge_k<<<CCLS, 256>>>(Wv, bv, Wo, bo, l);
    }
    combine_k<<<128, 256>>>(lw, lt, out);
}

// round 8
// speedup vs baseline: 1.0126x; 1.0126x over previous
#include <cuda_runtime.h>
#include <cuda_bf16.h>
#include <math.h>
#include <stdint.h>

#define NSUP 65536
#define EDIM 512
#define CCLS 64
#define HEADS 8
#define DHEAD 64
#define LVLS 3
#define SLOT 2048
#define NPART 8

// ---------------- scratch (device globals; no allocation) ----------------
__device__ float g_t[(size_t)NSUP * EDIM];
__device__ float g_feat[(size_t)CCLS * SLOT * EDIM];
__device__ float g_mu[NSUP];
__device__ float g_rstd[NSUP];
__device__ int   g_pos[NSUP];
__device__ int   g_count[CCLS];
__device__ float g_proto[(size_t)LVLS * CCLS * EDIM];
__device__ float g_lns[4][NSUP];
__device__ float g_lnq[4][NSUP];
__device__ float g_ctx[CCLS * EDIM];
__device__ float g_uvec[CCLS * HEADS * EDIM];
__device__ float g_pm[CCLS * NPART * HEADS];
__device__ float g_pl[CCLS * NPART * HEADS];
__device__ float g_pacc[(size_t)CCLS * NPART * HEADS * EDIM];
__device__ __nv_bfloat16 g_xhi[(size_t)NSUP * EDIM];
__device__ __nv_bfloat16 g_xlo[(size_t)NSUP * EDIM];
__device__ __nv_bfloat16 g_ahi[(size_t)NSUP * EDIM];
__device__ __nv_bfloat16 g_alo[(size_t)NSUP * EDIM];
__device__ __nv_bfloat16 g_wh[(size_t)6 * EDIM * EDIM];   // W^T splits: [mat][n][k]
__device__ __nv_bfloat16 g_wl[(size_t)6 * EDIM * EDIM];

// ---------------- PTX helpers ----------------
__device__ __forceinline__ uint32_t smem_u32(const void* p) {
    uint32_t a;
    asm("{ .reg .u64 t; cvta.to.shared.u64 t, %1; cvt.u32.u64 %0, t; }" : "=r"(a) : "l"(p));
    return a;
}
__device__ __forceinline__ void cpa16(uint32_t s, const void* g) {
    asm volatile("cp.async.cg.shared.global [%0], [%1], 16;" :: "r"(s), "l"(g));
}
__device__ __forceinline__ void cpa_commit() { asm volatile("cp.async.commit_group;" ::: "memory"); }
template<int N>
__device__ __forceinline__ void cpa_wait() { asm volatile("cp.async.wait_group %0;" :: "n"(N) : "memory"); }
__device__ __forceinline__ void ldmx4(uint32_t* r, uint32_t a) {
    asm volatile("ldmatrix.sync.aligned.m8n8.x4.shared.b16 {%0,%1,%2,%3}, [%4];"
        : "=r"(r[0]), "=r"(r[1]), "=r"(r[2]), "=r"(r[3]) : "r"(a));
}
__device__ __forceinline__ void mma16816(float* c, const uint32_t* a, uint32_t b0, uint32_t b1) {
    asm volatile("mma.sync.aligned.m16n8k16.row.col.f32.bf16.bf16.f32 "
        "{%0,%1,%2,%3}, {%4,%5,%6,%7}, {%8,%9}, {%0,%1,%2,%3};"
        : "+f"(c[0]), "+f"(c[1]), "+f"(c[2]), "+f"(c[3])
        : "r"(a[0]), "r"(a[1]), "r"(a[2]), "r"(a[3]), "r"(b0), "r"(b1));
}

// ---------------- build class membership ----------------
__global__ void __launch_bounds__(256) build_k(const int* __restrict__ labels) {
    __shared__ int warp_cnt[8];
    __shared__ int s_base;
    int tid = threadIdx.x, lane = tid & 31, w = tid >> 5;
    int c = blockIdx.x;
    if (tid == 0) s_base = 0;
    __syncthreads();
    for (int base = 0; base < NSUP; base += 256) {
        int n = base + tid;
        bool f = (labels[n] == c);
        unsigned m = __ballot_sync(0xffffffffu, f);
        if (lane == 0) warp_cnt[w] = __popc(m);
        __syncthreads();
        int woff = 0, tot = 0;
        #pragma unroll
        for (int i = 0; i < 8; i++) { int v = warp_cnt[i]; if (i < w) woff += v; tot += v; }
        if (f) g_pos[n] = c * SLOT + s_base + woff + __popc(m & ((1u << lane) - 1u));
        __syncthreads();
        if (tid == 0) s_base += tot;
        __syncthreads();
    }
    if (tid == 0) g_count[c] = s_base;
}

// ---------------- bf16 splits ----------------
__global__ void __launch_bounds__(256) xsplit_k(const float* __restrict__ X) {
    size_t i = (size_t)blockIdx.x * 256 + threadIdx.x;   // float4 index
    float4 v = ((const float4*)X)[i];
    __nv_bfloat16 h0 = __float2bfloat16(v.x), h1 = __float2bfloat16(v.y);
    __nv_bfloat16 h2 = __float2bfloat16(v.z), h3 = __float2bfloat16(v.w);
    __nv_bfloat16 l0 = __float2bfloat16(v.x - __bfloat162float(h0));
    __nv_bfloat16 l1 = __float2bfloat16(v.y - __bfloat162float(h1));
    __nv_bfloat16 l2 = __float2bfloat16(v.z - __bfloat162float(h2));
    __nv_bfloat16 l3 = __float2bfloat16(v.w - __bfloat162float(h3));
    uint2 ph, pl;
    ph.x = (uint32_t)__bfloat16_as_ushort(h0) | ((uint32_t)__bfloat16_as_ushort(h1) << 16);
    ph.y = (uint32_t)__bfloat16_as_ushort(h2) | ((uint32_t)__bfloat16_as_ushort(h3) << 16);
    pl.x = (uint32_t)__bfloat16_as_ushort(l0) | ((uint32_t)__bfloat16_as_ushort(l1) << 16);
    pl.y = (uint32_t)__bfloat16_as_ushort(l2) | ((uint32_t)__bfloat16_as_ushort(l3) << 16);
    ((uint2*)g_xhi)[i] = ph;
    ((uint2*)g_xlo)[i] = pl;
}

__global__ void __launch_bounds__(256) wsplit_k(const float* __restrict__ W1, const float* __restrict__ W2) {
    int m = blockIdx.y;            // 0..5
    int idx = blockIdx.x * 256 + threadIdx.x;   // < 512*512
    int k = idx >> 9, n = idx & 511;
    const float* src = (m < 3) ? (W1 + (size_t)m * EDIM * EDIM) : (W2 + (size_t)(m - 3) * EDIM * EDIM);
    float v = src[(size_t)k * EDIM + n];
    __nv_bfloat16 h = __float2bfloat16(v);
    __nv_bfloat16 l = __float2bfloat16(v - __bfloat162float(h));
    size_t dst = (size_t)m * EDIM * EDIM + (size_t)n * EDIM + k;   // transpose
    g_wh[dst] = h;
    g_wl[dst] = l;
}

// ---------------- LN stats from partials ----------------
__global__ void __launch_bounds__(256) ln2_k() {
    int row = blockIdx.x * 256 + threadIdx.x;
    float s = g_lns[0][row] + g_lns[1][row] + g_lns[2][row] + g_lns[3][row];
    float q = g_lnq[0][row] + g_lnq[1][row] + g_lnq[2][row] + g_lnq[3][row];
    float mu = s * (1.f / EDIM);
    float var = q * (1.f / EDIM) - mu * mu;
    g_mu[row] = mu;
    g_rstd[row] = rsqrtf(var + 1e-5f);
}

// ---------------- LN + ReLU + bf16 split of activations ----------------
__global__ void __launch_bounds__(256) actsplit_k(const float* __restrict__ gamma, const float* __restrict__ beta) {
    size_t i = (size_t)blockIdx.x * 256 + threadIdx.x;   // float4 index
    float4 v = ((const float4*)g_t)[i];
    int row = (int)(i >> 7);
    int col = ((int)i & 127) * 4;
    float mu = g_mu[row], rs = g_rstd[row];
    float4 gg = *(const float4*)(gamma + col);
    float4 bb = *(const float4*)(beta + col);
    float a0 = fmaxf(fmaf((v.x - mu) * rs, gg.x, bb.x), 0.f);
    float a1 = fmaxf(fmaf((v.y - mu) * rs, gg.y, bb.y), 0.f);
    float a2 = fmaxf(fmaf((v.z - mu) * rs, gg.z, bb.z), 0.f);
    float a3 = fmaxf(fmaf((v.w - mu) * rs, gg.w, bb.w), 0.f);
    __nv_bfloat16 h0 = __float2bfloat16(a0), h1 = __float2bfloat16(a1);
    __nv_bfloat16 h2 = __float2bfloat16(a2), h3 = __float2bfloat16(a3);
    __nv_bfloat16 l0 = __float2bfloat16(a0 - __bfloat162float(h0));
    __nv_bfloat16 l1 = __float2bfloat16(a1 - __bfloat162float(h1));
    __nv_bfloat16 l2 = __float2bfloat16(a2 - __bfloat162float(h2));
    __nv_bfloat16 l3 = __float2bfloat16(a3 - __bfloat162float(h3));
    uint2 ph, pl;
    ph.x = (uint32_t)__bfloat16_as_ushort(h0) | ((uint32_t)__bfloat16_as_ushort(h1) << 16);
    ph.y = (uint32_t)__bfloat16_as_ushort(h2) | ((uint32_t)__bfloat16_as_ushort(h3) << 16);
    pl.x = (uint32_t)__bfloat16_as_ushort(l0) | ((uint32_t)__bfloat16_as_ushort(l1) << 16);
    pl.y = (uint32_t)__bfloat16_as_ushort(l2) | ((uint32_t)__bfloat16_as_ushort(l3) << 16);
    ((uint2*)g_ahi)[i] = ph;
    ((uint2*)g_alo)[i] = pl;
}

// ---------------- mma.sync GEMM: C[65536x512] = A @ W   (bf16 hi/lo 3-pass, fp32 accum) ----------------
// CTA tile 128x128, 128 threads, 4 warps (2x2), warp tile 64x64, K-chunk 32, cp.async double buffer.
// 16 LDSM.x4 feed 96 MMAs per K-step per warp (6 MMA/LDSM) to relieve the smem crossbar.
#define GM_NCH 16
#define GM_STRB 80                          // padded row stride in bytes (40 bf16)
#define GM_AH 0
#define GM_AL (128 * GM_STRB)               // 10240
#define GM_BH (2 * 128 * GM_STRB)           // 20480
#define GM_BL (3 * 128 * GM_STRB)           // 30720
#define GM_BUF (4 * 128 * GM_STRB)          // 40960 per buffer
#define GM_SMEM (2 * GM_BUF)                // 81920 B

template<int EPI>
__global__ void __launch_bounds__(128) gemm_mma_k(
    const __nv_bfloat16* __restrict__ Ahi, const __nv_bfloat16* __restrict__ Alo,
    const __nv_bfloat16* __restrict__ Bhi, const __nv_bfloat16* __restrict__ Blo,
    const float* __restrict__ bias, float* __restrict__ Cout)
{
    extern __shared__ char smem[];
    uint32_t sb = smem_u32(smem);
    int tid = threadIdx.x, lane = tid & 31, wid = tid >> 5;
    int wm = wid >> 1, wn = wid & 1;      // 2 x 2 warp grid; warp tile 64x64
    int row0 = blockIdx.x * 128, col0 = blockIdx.y * 128;

    float acc[4][8][4];                   // [mb][nb*2+half][frag] = 128 regs
    #pragma unroll
    for (int i = 0; i < 4; i++)
        #pragma unroll
        for (int j = 0; j < 8; j++)
            #pragma unroll
            for (int t = 0; t < 4; t++) acc[i][j][t] = 0.f;

    // per-warp ldmatrix base offsets
    int lr = lane & 15, lc = lane >> 4;
    uint32_t a_off = (uint32_t)((wm * 64 + lr) * GM_STRB + lc * 16);
    uint32_t b_off = (uint32_t)(GM_BH + (wn * 64 + lr) * GM_STRB + lc * 16);

    auto load_chunk = [&](int ch) {
        uint32_t s0 = sb + (ch & 1) * GM_BUF;
        int k0 = ch * 32;
        #pragma unroll
        for (int it = 0; it < 4; it++) {
            int u = tid + it * 128;
            int r = u >> 2, sg = u & 3;
            uint32_t so = (uint32_t)(r * GM_STRB + sg * 16);
            size_t ga = (size_t)(row0 + r) * EDIM + k0 + sg * 8;
            size_t gb = (size_t)(col0 + r) * EDIM + k0 + sg * 8;
            cpa16(s0 + GM_AH + so, Ahi + ga);
            cpa16(s0 + GM_AL + so, Alo + ga);
            cpa16(s0 + GM_BH + so, Bhi + gb);
            cpa16(s0 + GM_BL + so, Blo + gb);
        }
        cpa_commit();
    };

    load_chunk(0);
    load_chunk(1);

    for (int ch = 0; ch < GM_NCH; ch++) {
        if (ch == GM_NCH - 1) cpa_wait<0>(); else cpa_wait<1>();
        __syncthreads();
        uint32_t s0 = sb + (ch & 1) * GM_BUF;
        #pragma unroll
        for (int ks = 0; ks < 2; ks++) {
            uint32_t ah[4][4], al[4][4];
            #pragma unroll
            for (int mb = 0; mb < 4; mb++) {
                uint32_t ra = s0 + a_off + (uint32_t)(mb * 16 * GM_STRB + ks * 32);
                ldmx4(ah[mb], ra);
                ldmx4(al[mb], ra + GM_AL);
            }
            #pragma unroll
            for (int nb = 0; nb < 4; nb++) {
                uint32_t rb = s0 + b_off + (uint32_t)(nb * 16 * GM_STRB + ks * 32);
                uint32_t bh[4], bl[4];
                ldmx4(bh, rb);
                ldmx4(bl, rb + (GM_BL - GM_BH));
                #pragma unroll
                for (int mb = 0; mb < 4; mb++) {
                    mma16816(acc[mb][nb * 2],     ah[mb], bh[0], bh[2]);
                    mma16816(acc[mb][nb * 2],     al[mb], bh[0], bh[2]);
                    mma16816(acc[mb][nb * 2],     ah[mb], bl[0], bl[2]);
                    mma16816(acc[mb][nb * 2 + 1], ah[mb], bh[1], bh[3]);
                    mma16816(acc[mb][nb * 2 + 1], al[mb], bh[1], bh[3]);
                    mma16816(acc[mb][nb * 2 + 1], ah[mb], bl[1], bl[3]);
                }
            }
        }
        __syncthreads();
        if (ch + 2 < GM_NCH) load_chunk(ch + 2);
    }

    // epilogue: bias add; EPI0: dense rows + LN partial sums; EPI1: scatter via g_pos
    float* s_sum = (float*)smem;            // 128 rows x 2 warps (dead buffer 0)
    float* s_sq  = (float*)(smem + 2048);
    #pragma unroll
    for (int mb = 0; mb < 4; mb++) {
        int rl = wm * 64 + mb * 16 + (lane >> 2);
        size_t dr0, dr1;
        if (EPI == 0) { dr0 = (size_t)(row0 + rl); dr1 = (size_t)(row0 + rl + 8); }
        else          { dr0 = (size_t)g_pos[row0 + rl]; dr1 = (size_t)g_pos[row0 + rl + 8]; }
        float* d0 = Cout + dr0 * EDIM;
        float* d1 = Cout + dr1 * EDIM;
        float rs0 = 0.f, rq0 = 0.f, rs1 = 0.f, rq1 = 0.f;
        #pragma unroll
        for (int j = 0; j < 8; j++) {
            int col = col0 + wn * 64 + (j >> 1) * 16 + (j & 1) * 8 + (lane & 3) * 2;
            float2 bb = *(const float2*)(bias + col);
            float2 o0, o1;
            o0.x = acc[mb][j][0] + bb.x; o0.y = acc[mb][j][1] + bb.y;
            o1.x = acc[mb][j][2] + bb.x; o1.y = acc[mb][j][3] + bb.y;
            *(float2*)(d0 + col) = o0;
            *(float2*)(d1 + col) = o1;
            if (EPI == 0) {
                rs0 += o0.x + o0.y; rq0 += o0.x * o0.x + o0.y * o0.y;
                rs1 += o1.x + o1.y; rq1 += o1.x * o1.x + o1.y * o1.y;
            }
        }
        if (EPI == 0) {
            rs0 += __shfl_xor_sync(0xffffffffu, rs0, 1); rs0 += __shfl_xor_sync(0xffffffffu, rs0, 2);
            rq0 += __shfl_xor_sync(0xffffffffu, rq0, 1); rq0 += __shfl_xor_sync(0xffffffffu, rq0, 2);
            rs1 += __shfl_xor_sync(0xffffffffu, rs1, 1); rs1 += __shfl_xor_sync(0xffffffffu, rs1, 2);
            rq1 += __shfl_xor_sync(0xffffffffu, rq1, 1); rq1 += __shfl_xor_sync(0xffffffffu, rq1, 2);
            if ((lane & 3) == 0) {
                s_sum[rl * 2 + wn] = rs0;       s_sq[rl * 2 + wn] = rq0;
                s_sum[(rl + 8) * 2 + wn] = rs1; s_sq[(rl + 8) * 2 + wn] = rq1;
            }
        }
    }
    if (EPI == 0) {
        __syncthreads();
        // 128 threads: one row each
        float s = s_sum[tid * 2] + s_sum[tid * 2 + 1];
        float q = s_sq[tid * 2] + s_sq[tid * 2 + 1];
        g_lns[blockIdx.y][row0 + tid] = s;
        g_lnq[blockIdx.y][row0 + tid] = q;
    }
}

// ---------------- attention part 1: per-class column means ----------------
__global__ void __launch_bounds__(256) colsum_k() {
    __shared__ float red[256];
    int tid = threadIdx.x;
    int c = blockIdx.x, col0 = blockIdx.y * 128;
    int M = g_count[c];
    const float* fbase = g_feat + (size_t)c * SLOT * EDIM;
    int half = tid >> 7, colx = tid & 127;
    float s = 0.f;
    for (int i = half; i < M; i += 2) s += fbase[(size_t)i * EDIM + col0 + colx];
    red[tid] = s;
    __syncthreads();
    if (tid < 128) g_ctx[c * EDIM + col0 + tid] = (red[tid] + red[tid + 128]) / (float)M;
}

// ---------------- attention part 2: q then projected u vectors ----------------
__global__ void __launch_bounds__(256) qu_k(const float* __restrict__ Wq, const float* __restrict__ bq,
                                            const float* __restrict__ Wk) {
    __shared__ float CTX[512];
    __shared__ float Q[512];
    int tid = threadIdx.x;
    int c = blockIdx.x;
    CTX[tid] = g_ctx[c * EDIM + tid];
    CTX[tid + 256] = g_ctx[c * EDIM + tid + 256];
    __syncthreads();
    {
        float q0 = bq[tid], q1 = bq[tid + 256];
        for (int k = 0; k < EDIM; k++) {
            float cv = CTX[k];
            q0 = fmaf(cv, Wq[(size_t)k * EDIM + tid], q0);
            q1 = fmaf(cv, Wq[(size_t)k * EDIM + tid + 256], q1);
        }
        Q[tid] = q0; Q[tid + 256] = q1;
    }
    __syncthreads();
    // u_h = scale * Wk[:, h-block] @ q_h (bk dropped: softmax shift invariance)
    for (int idx = tid; idx < HEADS * EDIM; idx += 256) {
        int h = idx >> 9, e = idx & 511;
        const float* wk = Wk + (size_t)e * EDIM + h * DHEAD;
        const float* qh = Q + h * DHEAD;
        float s = 0.f;
        #pragma unroll 8
        for (int d = 0; d < DHEAD; d++) s = fmaf(wk[d], qh[d], s);
        g_uvec[c * HEADS * EDIM + idx] = s * 0.125f;
    }
}

// ---------------- attention part 3: partial online softmax (grid CCLS x NPART) ----------------
#define AP_SMEM ((4096 + 2 * 8192) * 4)   // U + FS double buffer = 81920 B

__global__ void __launch_bounds__(256) attn_part_k() {
    extern __shared__ float sm[];
    float* U  = sm;          // 8*512
    float* FS = sm + 4096;   // 2*16*512

    int tid = threadIdx.x, lane = tid & 31, w = tid >> 5;
    int c = blockIdx.x, p = blockIdx.y;
    int M = g_count[c];
    const float* fbase = g_feat + (size_t)c * SLOT * EDIM;

    for (int i = tid; i < 1024; i += 256)
        ((float4*)U)[i] = ((const float4*)(g_uvec + (size_t)c * HEADS * EDIM))[i];
    __syncthreads();

    float u4r[16], acc_r[16];
    {
        const float4* U4 = (const float4*)(U + w * EDIM);
        #pragma unroll
        for (int q = 0; q < 4; q++) {
            float4 uu = U4[lane + 32 * q];
            u4r[4*q+0] = uu.x; u4r[4*q+1] = uu.y; u4r[4*q+2] = uu.z; u4r[4*q+3] = uu.w;
            acc_r[4*q+0] = 0.f; acc_r[4*q+1] = 0.f; acc_r[4*q+2] = 0.f; acc_r[4*q+3] = 0.f;
        }
    }
    float mmax = -3.0e38f, lsum = 0.f;

    int nch = (M + 15) >> 4;
    auto load_chunk = [&](int ch, int bsel) {
        int rbase = ch * 16;
        #pragma unroll
        for (int jj = 0; jj < 8; jj++) {
            int vid = tid + jj * 256;
            int r = vid >> 7;
            int c4 = vid & 127;
            if (rbase + r < M) {
                float4 v = *(const float4*)(fbase + (size_t)(rbase + r) * EDIM + c4 * 4);
                *(float4*)(FS + bsel * 8192 + r * 512 + c4 * 4) = v;
            }
        }
    };
    if (p < nch) load_chunk(p, 0);
    __syncthreads();
    int it = 0;
    for (int ch = p; ch < nch; ch += NPART, it ^= 1) {
        if (ch + NPART < nch) load_chunk(ch + NPART, it ^ 1);
        int rem = M - ch * 16; if (rem > 16) rem = 16;
        float* fsb = FS + it * 8192;
        float sv[16];
        #pragma unroll
        for (int i = 0; i < 16; i++) {
            if (i < rem) {
                const float4* fr = (const float4*)(fsb + i * 512);
                float d = 0.f;
                #pragma unroll
                for (int q = 0; q < 4; q++) {
                    float4 f = fr[lane + 32 * q];
                    d = fmaf(f.x, u4r[4*q+0], d);
                    d = fmaf(f.y, u4r[4*q+1], d);
                    d = fmaf(f.z, u4r[4*q+2], d);
                    d = fmaf(f.w, u4r[4*q+3], d);
                }
                #pragma unroll
                for (int o = 16; o > 0; o >>= 1) d += __shfl_xor_sync(0xffffffffu, d, o);
                sv[i] = d;
            } else sv[i] = -3.0e38f;
        }
        float m_c = sv[0];
        #pragma unroll
        for (int i = 1; i < 16; i++) m_c = fmaxf(m_c, sv[i]);
        float newmax = fmaxf(mmax, m_c);
        float fac = __expf(mmax - newmax);
        lsum *= fac;
        #pragma unroll
        for (int j = 0; j < 16; j++) acc_r[j] *= fac;
        #pragma unroll
        for (int i = 0; i < 16; i++) {
            if (i < rem) {
                float pex = __expf(sv[i] - newmax);
                lsum += pex;
                const float4* fr = (const float4*)(fsb + i * 512);
                #pragma unroll
                for (int q = 0; q < 4; q++) {
                    float4 f = fr[lane + 32 * q];
                    acc_r[4*q+0] = fmaf(pex, f.x, acc_r[4*q+0]);
                    acc_r[4*q+1] = fmaf(pex, f.y, acc_r[4*q+1]);
                    acc_r[4*q+2] = fmaf(pex, f.z, acc_r[4*q+2]);
                    acc_r[4*q+3] = fmaf(pex, f.w, acc_r[4*q+3]);
                }
            }
        }
        mmax = newmax;
        __syncthreads();
    }
    size_t base = (size_t)(c * NPART + p) * HEADS + w;
    if (lane == 0) { g_pm[base] = mmax; g_pl[base] = lsum; }
    float4* P4 = (float4*)(g_pacc + base * EDIM);
    #pragma unroll
    for (int q = 0; q < 4; q++) {
        float4 o;
        o.x = acc_r[4*q+0]; o.y = acc_r[4*q+1]; o.z = acc_r[4*q+2]; o.w = acc_r[4*q+3];
        P4[lane + 32 * q] = o;
    }
}

// ---------------- attention part 4: merge partials + Wv + Wo ----------------
__global__ void __launch_bounds__(256) merge_k(const float* __restrict__ Wv, const float* __restrict__ bv,
                                               const float* __restrict__ Wo, const float* __restrict__ bo,
                                               int level) {
    __shared__ float ACCA[HEADS * EDIM];
    __shared__ float OUTS[EDIM];
    int tid = threadIdx.x, lane = tid & 31, w = tid >> 5;
    int c = blockIdx.x;

    // warp w merges head w
    {
        float mp[NPART], lp[NPART];
        float gm = -3.0e38f;
        #pragma unroll
        for (int p = 0; p < NPART; p++) {
            size_t b = (size_t)(c * NPART + p) * HEADS + w;
            mp[p] = g_pm[b]; lp[p] = g_pl[b];
            gm = fmaxf(gm, mp[p]);
        }
        float coef[NPART];
        float L = 0.f;
        #pragma unroll
        for (int p = 0; p < NPART; p++) { coef[p] = __expf(mp[p] - gm); L += lp[p] * coef[p]; }
        float invL = 1.f / L;
        #pragma unroll
        for (int q = 0; q < 4; q++) {
            int e4 = lane + 32 * q;
            float4 s = make_float4(0.f, 0.f, 0.f, 0.f);
            #pragma unroll
            for (int p = 0; p < NPART; p++) {
                size_t b = (size_t)(c * NPART + p) * HEADS + w;
                float4 v = ((const float4*)(g_pacc + b * EDIM))[e4];
                s.x = fmaf(coef[p], v.x, s.x); s.y = fmaf(coef[p], v.y, s.y);
                s.z = fmaf(coef[p], v.z, s.z); s.w = fmaf(coef[p], v.w, s.w);
            }
            float4 o;
            o.x = s.x * invL; o.y = s.y * invL; o.z = s.z * invL; o.w = s.w * invL;
            ((float4*)(ACCA + w * EDIM))[e4] = o;
        }
    }
    __syncthreads();

    // out = concat_h[(attn-weighted feat) @ Wv_h] + bv
    {
        int o0 = tid, o1 = tid + 256;
        int h0 = o0 >> 6, h1 = o1 >> 6;
        float a0 = bv[o0], a1 = bv[o1];
        for (int e = 0; e < EDIM; e++) {
            a0 = fmaf(ACCA[h0 * EDIM + e], Wv[(size_t)e * EDIM + o0], a0);
            a1 = fmaf(ACCA[h1 * EDIM + e], Wv[(size_t)e * EDIM + o1], a1);
        }
        OUTS[o0] = a0; OUTS[o1] = a1;
    }
    __syncthreads();

    // proto = out @ Wo + bo
    {
        int o0 = tid, o1 = tid + 256;
        float p0 = bo[o0], p1 = bo[o1];
        for (int e = 0; e < EDIM; e++) {
            float ov = OUTS[e];
            p0 = fmaf(ov, Wo[(size_t)e * EDIM + o0], p0);
            p1 = fmaf(ov, Wo[(size_t)e * EDIM + o1], p1);
        }
        size_t pb = ((size_t)level * CCLS + c) * EDIM;
        g_proto[pb + o0] = p0;
        g_proto[pb + o1] = p1;
    }
}

// ---------------- final combine ----------------
__global__ void __launch_bounds__(256) combine_k(const float* __restrict__ lw,
                                                 const float* __restrict__ lt,
                                                 float* __restrict__ out) {
    int idx = blockIdx.x * 256 + threadIdx.x;
    float a0 = lw[0], a1 = lw[1], a2 = lw[2];
    float mx = fmaxf(a0, fmaxf(a1, a2));
    float e0 = expf(a0 - mx), e1 = expf(a1 - mx), e2 = expf(a2 - mx);
    float inv = 1.f / (e0 + e1 + e2);
    float w0 = e0 * inv / lt[0], w1 = e1 * inv / lt[1], w2 = e2 * inv / lt[2];
    out[idx] = g_proto[idx] * w0
             + g_proto[(size_t)CCLS * EDIM + idx] * w1
             + g_proto[(size_t)2 * CCLS * EDIM + idx] * w2;
}

// ---------------- launch ----------------
extern "C" void kernel_launch(void* const* d_in, const int* in_sizes, int n_in,
                              void* d_out, int out_size) {
    (void)in_sizes; (void)n_in; (void)out_size;
    const float* X      = (const float*)d_in[0];
    const int*   labels = (const int*)d_in[1];
    const float* W1     = (const float*)d_in[2];
    const float* b1     = (const float*)d_in[3];
    const float* gamma  = (const float*)d_in[4];
    const float* beta   = (const float*)d_in[5];
    const float* W2     = (const float*)d_in[6];
    const float* b2     = (const float*)d_in[7];
    const float* Wq     = (const float*)d_in[8];
    const float* bq     = (const float*)d_in[9];
    const float* Wk     = (const float*)d_in[10];
    const float* Wv     = (const float*)d_in[12];
    const float* bv     = (const float*)d_in[13];
    const float* Wo     = (const float*)d_in[14];
    const float* bo     = (const float*)d_in[15];
    const float* lw     = (const float*)d_in[16];
    const float* lt     = (const float*)d_in[17];
    float* out = (float*)d_out;

    cudaFuncSetAttribute((const void*)gemm_mma_k<0>, cudaFuncAttributeMaxDynamicSharedMemorySize, GM_SMEM);
    cudaFuncSetAttribute((const void*)gemm_mma_k<1>, cudaFuncAttributeMaxDynamicSharedMemorySize, GM_SMEM);
    cudaFuncSetAttribute((const void*)attn_part_k, cudaFuncAttributeMaxDynamicSharedMemorySize, AP_SMEM);

    __nv_bfloat16 *pxhi, *pxlo, *pahi, *palo, *pwh, *pwl;
    float *pt, *pfeat;
    cudaGetSymbolAddress((void**)&pxhi, g_xhi);
    cudaGetSymbolAddress((void**)&pxlo, g_xlo);
    cudaGetSymbolAddress((void**)&pahi, g_ahi);
    cudaGetSymbolAddress((void**)&palo, g_alo);
    cudaGetSymbolAddress((void**)&pwh, g_wh);
    cudaGetSymbolAddress((void**)&pwl, g_wl);
    cudaGetSymbolAddress((void**)&pt, g_t);
    cudaGetSymbolAddress((void**)&pfeat, g_feat);

    build_k<<<64, 256>>>(labels);
    xsplit_k<<<(NSUP * EDIM / 4) / 256, 256>>>(X);
    wsplit_k<<<dim3(1024, 6), 256>>>(W1, W2);

    for (int l = 0; l < LVLS; l++) {
        const __nv_bfloat16* w1h = pwh + (size_t)l * EDIM * EDIM;
        const __nv_bfloat16* w1l = pwl + (size_t)l * EDIM * EDIM;
        const __nv_bfloat16* w2h = pwh + (size_t)(3 + l) * EDIM * EDIM;
        const __nv_bfloat16* w2l = pwl + (size_t)(3 + l) * EDIM * EDIM;
        gemm_mma_k<0><<<dim3(512, 4), 128, GM_SMEM>>>(pxhi, pxlo, w1h, w1l, b1 + l * EDIM, pt);
        ln2_k<<<256, 256>>>();
        actsplit_k<<<(NSUP * EDIM / 4) / 256, 256>>>(gamma + l * EDIM, beta + l * EDIM);
        gemm_mma_k<1><<<dim3(512, 4), 128, GM_SMEM>>>(pahi, palo, w2h, w2l, b2 + l * EDIM, pfeat);
        colsum_k<<<dim3(CCLS, 4), 256>>>();
        qu_k<<<CCLS, 256>>>(Wq, bq, Wk);
        attn_part_k<<<dim3(CCLS, NPART), 256, AP_SMEM>>>();
        merge_k<<<CCLS, 256>>>(Wv, bv, Wo, bo, l);
    }
    combine_k<<<128, 256>>>(lw, lt, out);
}

// round 13
// speedup vs baseline: 1.2173x; 1.2022x over previous
#include <cuda_runtime.h>
#include <cuda_bf16.h>
#include <math.h>
#include <stdint.h>

#define NSUP 65536
#define EDIM 512
#define CCLS 64
#define HEADS 8
#define DHEAD 64
#define LVLS 3
#define SLOT 2048
#define NPART 8
#define PLANE_T ((size_t)NSUP * EDIM)
#define PLANE_F ((size_t)CCLS * SLOT * EDIM)

// ---------------- scratch (device globals; no allocation) ----------------
__device__ float g_t[LVLS * PLANE_T];
__device__ float g_feat[LVLS * PLANE_F];
__device__ float g_mu[LVLS * NSUP];
__device__ float g_rstd[LVLS * NSUP];
__device__ int   g_pos[NSUP];
__device__ int   g_count[CCLS];
__device__ float g_proto[(size_t)LVLS * CCLS * EDIM];
__device__ float g_lns[4][LVLS * NSUP];
__device__ float g_lnq[4][LVLS * NSUP];
__device__ float g_ctx[LVLS * CCLS * EDIM];
__device__ float g_uvec[(size_t)LVLS * CCLS * HEADS * EDIM];
__device__ float g_pm[LVLS * CCLS * NPART * HEADS];
__device__ float g_pl[LVLS * CCLS * NPART * HEADS];
__device__ float g_pacc[(size_t)LVLS * CCLS * NPART * HEADS * EDIM];
__device__ __nv_bfloat16 g_xhi[PLANE_T];
__device__ __nv_bfloat16 g_xlo[PLANE_T];
__device__ __nv_bfloat16 g_ahi[LVLS * PLANE_T];
__device__ __nv_bfloat16 g_alo[LVLS * PLANE_T];
__device__ __nv_bfloat16 g_wh[(size_t)6 * EDIM * EDIM];   // W^T splits: [mat][n][k]
__device__ __nv_bfloat16 g_wl[(size_t)6 * EDIM * EDIM];

// ---------------- PTX helpers ----------------
__device__ __forceinline__ uint32_t smem_u32(const void* p) {
    uint32_t a;
    asm("{ .reg .u64 t; cvta.to.shared.u64 t, %1; cvt.u32.u64 %0, t; }" : "=r"(a) : "l"(p));
    return a;
}
__device__ __forceinline__ void cpa16(uint32_t s, const void* g) {
    asm volatile("cp.async.cg.shared.global [%0], [%1], 16;" :: "r"(s), "l"(g));
}
__device__ __forceinline__ void cpa_commit() { asm volatile("cp.async.commit_group;" ::: "memory"); }
template<int N>
__device__ __forceinline__ void cpa_wait() { asm volatile("cp.async.wait_group %0;" :: "n"(N) : "memory"); }
__device__ __forceinline__ void ldmx4(uint32_t* r, uint32_t a) {
    asm volatile("ldmatrix.sync.aligned.m8n8.x4.shared.b16 {%0,%1,%2,%3}, [%4];"
        : "=r"(r[0]), "=r"(r[1]), "=r"(r[2]), "=r"(r[3]) : "r"(a));
}
__device__ __forceinline__ void mma16816(float* c, const uint32_t* a, uint32_t b0, uint32_t b1) {
    asm volatile("mma.sync.aligned.m16n8k16.row.col.f32.bf16.bf16.f32 "
        "{%0,%1,%2,%3}, {%4,%5,%6,%7}, {%8,%9}, {%0,%1,%2,%3};"
        : "+f"(c[0]), "+f"(c[1]), "+f"(c[2]), "+f"(c[3])
        : "r"(a[0]), "r"(a[1]), "r"(a[2]), "r"(a[3]), "r"(b0), "r"(b1));
}

// ---------------- build class membership ----------------
__global__ void __launch_bounds__(256) build_k(const int* __restrict__ labels) {
    __shared__ int warp_cnt[8];
    __shared__ int s_base;
    int tid = threadIdx.x, lane = tid & 31, w = tid >> 5;
    int c = blockIdx.x;
    if (tid == 0) s_base = 0;
    __syncthreads();
    for (int base = 0; base < NSUP; base += 256) {
        int n = base + tid;
        bool f = (labels[n] == c);
        unsigned m = __ballot_sync(0xffffffffu, f);
        if (lane == 0) warp_cnt[w] = __popc(m);
        __syncthreads();
        int woff = 0, tot = 0;
        #pragma unroll
        for (int i = 0; i < 8; i++) { int v = warp_cnt[i]; if (i < w) woff += v; tot += v; }
        if (f) g_pos[n] = c * SLOT + s_base + woff + __popc(m & ((1u << lane) - 1u));
        __syncthreads();
        if (tid == 0) s_base += tot;
        __syncthreads();
    }
    if (tid == 0) g_count[c] = s_base;
}

// ---------------- bf16 splits ----------------
__global__ void __launch_bounds__(256) xsplit_k(const float* __restrict__ X) {
    size_t i = (size_t)blockIdx.x * 256 + threadIdx.x;   // float4 index
    float4 v = ((const float4*)X)[i];
    __nv_bfloat16 h0 = __float2bfloat16(v.x), h1 = __float2bfloat16(v.y);
    __nv_bfloat16 h2 = __float2bfloat16(v.z), h3 = __float2bfloat16(v.w);
    __nv_bfloat16 l0 = __float2bfloat16(v.x - __bfloat162float(h0));
    __nv_bfloat16 l1 = __float2bfloat16(v.y - __bfloat162float(h1));
    __nv_bfloat16 l2 = __float2bfloat16(v.z - __bfloat162float(h2));
    __nv_bfloat16 l3 = __float2bfloat16(v.w - __bfloat162float(h3));
    uint2 ph, pl;
    ph.x = (uint32_t)__bfloat16_as_ushort(h0) | ((uint32_t)__bfloat16_as_ushort(h1) << 16);
    ph.y = (uint32_t)__bfloat16_as_ushort(h2) | ((uint32_t)__bfloat16_as_ushort(h3) << 16);
    pl.x = (uint32_t)__bfloat16_as_ushort(l0) | ((uint32_t)__bfloat16_as_ushort(l1) << 16);
    pl.y = (uint32_t)__bfloat16_as_ushort(l2) | ((uint32_t)__bfloat16_as_ushort(l3) << 16);
    ((uint2*)g_xhi)[i] = ph;
    ((uint2*)g_xlo)[i] = pl;
}

__global__ void __launch_bounds__(256) wsplit_k(const float* __restrict__ W1, const float* __restrict__ W2) {
    int m = blockIdx.y;            // 0..5
    int idx = blockIdx.x * 256 + threadIdx.x;   // < 512*512
    int k = idx >> 9, n = idx & 511;
    const float* src = (m < 3) ? (W1 + (size_t)m * EDIM * EDIM) : (W2 + (size_t)(m - 3) * EDIM * EDIM);
    float v = src[(size_t)k * EDIM + n];
    __nv_bfloat16 h = __float2bfloat16(v);
    __nv_bfloat16 l = __float2bfloat16(v - __bfloat162float(h));
    size_t dst = (size_t)m * EDIM * EDIM + (size_t)n * EDIM + k;   // transpose
    g_wh[dst] = h;
    g_wl[dst] = l;
}

// ---------------- LN stats from partials (all levels) ----------------
__global__ void __launch_bounds__(256) ln2_k() {
    int row = blockIdx.x * 256 + threadIdx.x;   // < LVLS*NSUP
    float s = g_lns[0][row] + g_lns[1][row] + g_lns[2][row] + g_lns[3][row];
    float q = g_lnq[0][row] + g_lnq[1][row] + g_lnq[2][row] + g_lnq[3][row];
    float mu = s * (1.f / EDIM);
    float var = q * (1.f / EDIM) - mu * mu;
    g_mu[row] = mu;
    g_rstd[row] = rsqrtf(var + 1e-5f);
}

// ---------------- LN + ReLU + bf16 split of activations (per level via blockIdx.y) ----------------
__global__ void __launch_bounds__(256) actsplit_k(const float* __restrict__ gammaL, const float* __restrict__ betaL) {
    int lvl = blockIdx.y;
    size_t i = (size_t)blockIdx.x * 256 + threadIdx.x;   // float4 index within plane
    size_t ip = (size_t)lvl * (PLANE_T / 4) + i;
    float4 v = ((const float4*)g_t)[ip];
    int row = (int)(i >> 7);
    int col = ((int)i & 127) * 4;
    const float* gamma = gammaL + lvl * EDIM;
    const float* beta  = betaL + lvl * EDIM;
    float mu = g_mu[lvl * NSUP + row], rs = g_rstd[lvl * NSUP + row];
    float4 gg = *(const float4*)(gamma + col);
    float4 bb = *(const float4*)(beta + col);
    float a0 = fmaxf(fmaf((v.x - mu) * rs, gg.x, bb.x), 0.f);
    float a1 = fmaxf(fmaf((v.y - mu) * rs, gg.y, bb.y), 0.f);
    float a2 = fmaxf(fmaf((v.z - mu) * rs, gg.z, bb.z), 0.f);
    float a3 = fmaxf(fmaf((v.w - mu) * rs, gg.w, bb.w), 0.f);
    __nv_bfloat16 h0 = __float2bfloat16(a0), h1 = __float2bfloat16(a1);
    __nv_bfloat16 h2 = __float2bfloat16(a2), h3 = __float2bfloat16(a3);
    __nv_bfloat16 l0 = __float2bfloat16(a0 - __bfloat162float(h0));
    __nv_bfloat16 l1 = __float2bfloat16(a1 - __bfloat162float(h1));
    __nv_bfloat16 l2 = __float2bfloat16(a2 - __bfloat162float(h2));
    __nv_bfloat16 l3 = __float2bfloat16(a3 - __bfloat162float(h3));
    uint2 ph, pl;
    ph.x = (uint32_t)__bfloat16_as_ushort(h0) | ((uint32_t)__bfloat16_as_ushort(h1) << 16);
    ph.y = (uint32_t)__bfloat16_as_ushort(h2) | ((uint32_t)__bfloat16_as_ushort(h3) << 16);
    pl.x = (uint32_t)__bfloat16_as_ushort(l0) | ((uint32_t)__bfloat16_as_ushort(l1) << 16);
    pl.y = (uint32_t)__bfloat16_as_ushort(l2) | ((uint32_t)__bfloat16_as_ushort(l3) << 16);
    ((uint2*)g_ahi)[ip] = ph;
    ((uint2*)g_alo)[ip] = pl;
}

// ---------------- mma.sync GEMM (level-batched via blockIdx.z) ----------------
// CTA tile 128x128, 8 warps (2x4), warp tile 64x32, K-chunk 32, cp.async double buffer.
#define GM_NCH 16
#define GM_STRB 80                          // padded row stride in bytes (40 bf16)
#define GM_AH 0
#define GM_AL (128 * GM_STRB)               // 10240
#define GM_BH (2 * 128 * GM_STRB)           // 20480
#define GM_BL (3 * 128 * GM_STRB)           // 30720
#define GM_BUF (4 * 128 * GM_STRB)          // 40960 per buffer
#define GM_SMEM (2 * GM_BUF)                // 81920 B

template<int EPI>
__global__ void __launch_bounds__(256, 2) gemm_mma_k(
    const __nv_bfloat16* __restrict__ Abase, const __nv_bfloat16* __restrict__ AbaseLo,
    const __nv_bfloat16* __restrict__ WhBase, const __nv_bfloat16* __restrict__ WlBase,
    const float* __restrict__ biasBase, float* __restrict__ CoutBase)
{
    extern __shared__ char smem[];
    uint32_t sb = smem_u32(smem);
    int tid = threadIdx.x, lane = tid & 31, wid = tid >> 5;
    int wm = wid >> 2, wn = wid & 3;      // 2 x 4 warp grid; warp tile 64x32
    int row0 = blockIdx.x * 128, col0 = blockIdx.y * 128;
    int z = blockIdx.z;

    const __nv_bfloat16* Ahi = Abase   + (EPI == 1 ? (size_t)z * PLANE_T : 0);
    const __nv_bfloat16* Alo = AbaseLo + (EPI == 1 ? (size_t)z * PLANE_T : 0);
    const __nv_bfloat16* Bhi = WhBase + (size_t)z * EDIM * EDIM;
    const __nv_bfloat16* Blo = WlBase + (size_t)z * EDIM * EDIM;
    const float* bias = biasBase + z * EDIM;
    float* Cout = CoutBase + (size_t)z * (EPI == 0 ? PLANE_T : PLANE_F);

    float acc[4][4][4];                   // [mb][nj][frag]
    #pragma unroll
    for (int i = 0; i < 4; i++)
        #pragma unroll
        for (int j = 0; j < 4; j++)
            #pragma unroll
            for (int t = 0; t < 4; t++) acc[i][j][t] = 0.f;

    int lr = lane & 15, lc = lane >> 4;
    uint32_t a_off = (uint32_t)((wm * 64 + lr) * GM_STRB + lc * 16);
    uint32_t b_off = (uint32_t)(GM_BH + (wn * 32 + lr) * GM_STRB + lc * 16);

    auto load_chunk = [&](int ch) {
        uint32_t s0 = sb + (ch & 1) * GM_BUF;
        int k0 = ch * 32;
        #pragma unroll
        for (int it = 0; it < 2; it++) {
            int u = tid + it * 256;
            int r = u >> 2, sg = u & 3;
            uint32_t so = (uint32_t)(r * GM_STRB + sg * 16);
            size_t ga = (size_t)(row0 + r) * EDIM + k0 + sg * 8;
            size_t gb = (size_t)(col0 + r) * EDIM + k0 + sg * 8;
            cpa16(s0 + GM_AH + so, Ahi + ga);
            cpa16(s0 + GM_AL + so, Alo + ga);
            cpa16(s0 + GM_BH + so, Bhi + gb);
            cpa16(s0 + GM_BL + so, Blo + gb);
        }
        cpa_commit();
    };

    load_chunk(0);
    load_chunk(1);

    for (int ch = 0; ch < GM_NCH; ch++) {
        if (ch == GM_NCH - 1) cpa_wait<0>(); else cpa_wait<1>();
        __syncthreads();
        uint32_t s0 = sb + (ch & 1) * GM_BUF;
        #pragma unroll
        for (int ks = 0; ks < 2; ks++) {
            uint32_t ah[4][4], al[4][4];
            #pragma unroll
            for (int mb = 0; mb < 4; mb++) {
                uint32_t ra = s0 + a_off + (uint32_t)(mb * 16 * GM_STRB + ks * 32);
                ldmx4(ah[mb], ra);
                ldmx4(al[mb], ra + GM_AL);
            }
            #pragma unroll
            for (int nb = 0; nb < 2; nb++) {
                uint32_t rb = s0 + b_off + (uint32_t)(nb * 16 * GM_STRB + ks * 32);
                uint32_t bh[4], bl[4];
                ldmx4(bh, rb);
                ldmx4(bl, rb + (GM_BL - GM_BH));
                #pragma unroll
                for (int mb = 0; mb < 4; mb++) {
                    mma16816(acc[mb][nb * 2],     ah[mb], bh[0], bh[2]);
                    mma16816(acc[mb][nb * 2],     al[mb], bh[0], bh[2]);
                    mma16816(acc[mb][nb * 2],     ah[mb], bl[0], bl[2]);
                    mma16816(acc[mb][nb * 2 + 1], ah[mb], bh[1], bh[3]);
                    mma16816(acc[mb][nb * 2 + 1], al[mb], bh[1], bh[3]);
                    mma16816(acc[mb][nb * 2 + 1], ah[mb], bl[1], bl[3]);
                }
            }
        }
        __syncthreads();
        if (ch + 2 < GM_NCH) load_chunk(ch + 2);
    }

    // epilogue: bias add; EPI0: dense rows + LN partial sums; EPI1: scatter via g_pos
    float* s_sum = (float*)smem;
    float* s_sq  = (float*)(smem + 2048);
    #pragma unroll
    for (int mb = 0; mb < 4; mb++) {
        int rl = wm * 64 + mb * 16 + (lane >> 2);
        size_t dr0, dr1;
        if (EPI == 0) { dr0 = (size_t)(row0 + rl); dr1 = (size_t)(row0 + rl + 8); }
        else          { dr0 = (size_t)g_pos[row0 + rl]; dr1 = (size_t)g_pos[row0 + rl + 8]; }
        float* d0 = Cout + dr0 * EDIM;
        float* d1 = Cout + dr1 * EDIM;
        float rs0 = 0.f, rq0 = 0.f, rs1 = 0.f, rq1 = 0.f;
        #pragma unroll
        for (int j = 0; j < 4; j++) {
            int col = col0 + wn * 32 + (j >> 1) * 16 + (j & 1) * 8 + (lane & 3) * 2;
            float2 bb = *(const float2*)(bias + col);
            float2 o0, o1;
            o0.x = acc[mb][j][0] + bb.x; o0.y = acc[mb][j][1] + bb.y;
            o1.x = acc[mb][j][2] + bb.x; o1.y = acc[mb][j][3] + bb.y;
            *(float2*)(d0 + col) = o0;
            *(float2*)(d1 + col) = o1;
            if (EPI == 0) {
                rs0 += o0.x + o0.y; rq0 += o0.x * o0.x + o0.y * o0.y;
                rs1 += o1.x + o1.y; rq1 += o1.x * o1.x + o1.y * o1.y;
            }
        }
        if (EPI == 0) {
            rs0 += __shfl_xor_sync(0xffffffffu, rs0, 1); rs0 += __shfl_xor_sync(0xffffffffu, rs0, 2);
            rq0 += __shfl_xor_sync(0xffffffffu, rq0, 1); rq0 += __shfl_xor_sync(0xffffffffu, rq0, 2);
            rs1 += __shfl_xor_sync(0xffffffffu, rs1, 1); rs1 += __shfl_xor_sync(0xffffffffu, rs1, 2);
            rq1 += __shfl_xor_sync(0xffffffffu, rq1, 1); rq1 += __shfl_xor_sync(0xffffffffu, rq1, 2);
            if ((lane & 3) == 0) {
                s_sum[rl * 4 + wn] = rs0;       s_sq[rl * 4 + wn] = rq0;
                s_sum[(rl + 8) * 4 + wn] = rs1; s_sq[(rl + 8) * 4 + wn] = rq1;
            }
        }
    }
    if (EPI == 0) {
        __syncthreads();
        if (tid < 128) {
            float s = s_sum[tid * 4] + s_sum[tid * 4 + 1] + s_sum[tid * 4 + 2] + s_sum[tid * 4 + 3];
            float q = s_sq[tid * 4] + s_sq[tid * 4 + 1] + s_sq[tid * 4 + 2] + s_sq[tid * 4 + 3];
            g_lns[blockIdx.y][z * NSUP + row0 + tid] = s;
            g_lnq[blockIdx.y][z * NSUP + row0 + tid] = q;
        }
    }
}

// ---------------- attention: ctx mean + q + projected u (fused; grid CCLS x LVLS) ----------------
__global__ void __launch_bounds__(512) ctxqu_k(const float* __restrict__ Wq, const float* __restrict__ bq,
                                               const float* __restrict__ Wk) {
    __shared__ float CTX[512];
    __shared__ float Q[512];
    int tid = threadIdx.x;
    int c = blockIdx.x, lvl = blockIdx.y;
    int M = g_count[c];
    const float* fbase = g_feat + (size_t)lvl * PLANE_F + (size_t)c * SLOT * EDIM;

    // ctx: each thread owns one column, coalesced full-row reads
    float s = 0.f;
    #pragma unroll 4
    for (int i = 0; i < M; i++) s += fbase[(size_t)i * EDIM + tid];
    CTX[tid] = s / (float)M;
    __syncthreads();

    // q = ctx @ Wq + bq
    float q = bq[tid];
    for (int k = 0; k < EDIM; k++) q = fmaf(CTX[k], Wq[(size_t)k * EDIM + tid], q);
    Q[tid] = q;
    __syncthreads();

    // u_h = scale * Wk[:, h-block] @ q_h (bk dropped: softmax shift invariance)
    size_t ub = ((size_t)lvl * CCLS + c) * HEADS * EDIM;
    #pragma unroll
    for (int it = 0; it < 8; it++) {
        int idx = tid + it * 512;
        int h = idx >> 9, e = idx & 511;
        const float* wk = Wk + (size_t)e * EDIM + h * DHEAD;
        const float* qh = Q + h * DHEAD;
        float d = 0.f;
        #pragma unroll 8
        for (int dd = 0; dd < DHEAD; dd++) d = fmaf(wk[dd], qh[dd], d);
        g_uvec[ub + idx] = d * 0.125f;
    }
}

// ---------------- attention: partial online softmax (grid CCLS x NPART x LVLS) ----------------
#define AP_SMEM (2 * 8192 * 4)   // FS double buffer = 65536 B

__global__ void __launch_bounds__(256) attn_part_k() {
    extern __shared__ float sm[];
    float* FS = sm;          // 2*16*512

    int tid = threadIdx.x, lane = tid & 31, w = tid >> 5;
    int c = blockIdx.x, p = blockIdx.y, lvl = blockIdx.z;
    int M = g_count[c];
    const float* fbase = g_feat + (size_t)lvl * PLANE_F + (size_t)c * SLOT * EDIM;

    float u4r[16], acc_r[16];
    {
        const float4* U4 = (const float4*)(g_uvec + ((size_t)lvl * CCLS + c) * HEADS * EDIM + w * EDIM);
        #pragma unroll
        for (int q = 0; q < 4; q++) {
            float4 uu = U4[lane + 32 * q];
            u4r[4*q+0] = uu.x; u4r[4*q+1] = uu.y; u4r[4*q+2] = uu.z; u4r[4*q+3] = uu.w;
            acc_r[4*q+0] = 0.f; acc_r[4*q+1] = 0.f; acc_r[4*q+2] = 0.f; acc_r[4*q+3] = 0.f;
        }
    }
    float mmax = -3.0e38f, lsum = 0.f;

    int nch = (M + 15) >> 4;
    auto load_chunk = [&](int ch, int bsel) {
        int rbase = ch * 16;
        #pragma unroll
        for (int jj = 0; jj < 8; jj++) {
            int vid = tid + jj * 256;
            int r = vid >> 7;
            int c4 = vid & 127;
            if (rbase + r < M) {
                float4 v = *(const float4*)(fbase + (size_t)(rbase + r) * EDIM + c4 * 4);
                *(float4*)(FS + bsel * 8192 + r * 512 + c4 * 4) = v;
            }
        }
    };
    if (p < nch) load_chunk(p, 0);
    __syncthreads();
    int it = 0;
    for (int ch = p; ch < nch; ch += NPART, it ^= 1) {
        if (ch + NPART < nch) load_chunk(ch + NPART, it ^ 1);
        int rem = M - ch * 16; if (rem > 16) rem = 16;
        float* fsb = FS + it * 8192;
        float sv[16];
        #pragma unroll
        for (int i = 0; i < 16; i++) {
            if (i < rem) {
                const float4* fr = (const float4*)(fsb + i * 512);
                float d = 0.f;
                #pragma unroll
                for (int q = 0; q < 4; q++) {
                    float4 f = fr[lane + 32 * q];
                    d = fmaf(f.x, u4r[4*q+0], d);
                    d = fmaf(f.y, u4r[4*q+1], d);
                    d = fmaf(f.z, u4r[4*q+2], d);
                    d = fmaf(f.w, u4r[4*q+3], d);
                }
                #pragma unroll
                for (int o = 16; o > 0; o >>= 1) d += __shfl_xor_sync(0xffffffffu, d, o);
                sv[i] = d;
            } else sv[i] = -3.0e38f;
        }
        float m_c = sv[0];
        #pragma unroll
        for (int i = 1; i < 16; i++) m_c = fmaxf(m_c, sv[i]);
        float newmax = fmaxf(mmax, m_c);
        float fac = __expf(mmax - newmax);
        lsum *= fac;
        #pragma unroll
        for (int j = 0; j < 16; j++) acc_r[j] *= fac;
        #pragma unroll
        for (int i = 0; i < 16; i++) {
            if (i < rem) {
                float pex = __expf(sv[i] - newmax);
                lsum += pex;
                const float4* fr = (const float4*)(fsb + i * 512);
                #pragma unroll
                for (int q = 0; q < 4; q++) {
                    float4 f = fr[lane + 32 * q];
                    acc_r[4*q+0] = fmaf(pex, f.x, acc_r[4*q+0]);
                    acc_r[4*q+1] = fmaf(pex, f.y, acc_r[4*q+1]);
                    acc_r[4*q+2] = fmaf(pex, f.z, acc_r[4*q+2]);
                    acc_r[4*q+3] = fmaf(pex, f.w, acc_r[4*q+3]);
                }
            }
        }
        mmax = newmax;
        __syncthreads();
    }
    size_t base = (((size_t)lvl * CCLS + c) * NPART + p) * HEADS + w;
    if (lane == 0) { g_pm[base] = mmax; g_pl[base] = lsum; }
    float4* P4 = (float4*)(g_pacc + base * EDIM);
    #pragma unroll
    for (int q = 0; q < 4; q++) {
        float4 o;
        o.x = acc_r[4*q+0]; o.y = acc_r[4*q+1]; o.z = acc_r[4*q+2]; o.w = acc_r[4*q+3];
        P4[lane + 32 * q] = o;
    }
}

// ---------------- attention: merge partials + Wv + Wo (grid CCLS x LVLS) ----------------
__global__ void __launch_bounds__(256) merge_k(const float* __restrict__ Wv, const float* __restrict__ bv,
                                               const float* __restrict__ Wo, const float* __restrict__ bo) {
    __shared__ float ACCA[HEADS * EDIM];
    __shared__ float OUTS[EDIM];
    int tid = threadIdx.x, lane = tid & 31, w = tid >> 5;
    int c = blockIdx.x, lvl = blockIdx.y;
    size_t cb = ((size_t)lvl * CCLS + c) * NPART;

    // warp w merges head w
    {
        float mp[NPART], lp[NPART];
        float gm = -3.0e38f;
        #pragma unroll
        for (int p = 0; p < NPART; p++) {
            size_t b = (cb + p) * HEADS + w;
            mp[p] = g_pm[b]; lp[p] = g_pl[b];
            gm = fmaxf(gm, mp[p]);
        }
        float coef[NPART];
        float L = 0.f;
        #pragma unroll
        for (int p = 0; p < NPART; p++) { coef[p] = __expf(mp[p] - gm); L += lp[p] * coef[p]; }
        float invL = 1.f / L;
        #pragma unroll
        for (int q = 0; q < 4; q++) {
            int e4 = lane + 32 * q;
            float4 s = make_float4(0.f, 0.f, 0.f, 0.f);
            #pragma unroll
            for (int p = 0; p < NPART; p++) {
                size_t b = (cb + p) * HEADS + w;
                float4 v = ((const float4*)(g_pacc + b * EDIM))[e4];
                s.x = fmaf(coef[p], v.x, s.x); s.y = fmaf(coef[p], v.y, s.y);
                s.z = fmaf(coef[p], v.z, s.z); s.w = fmaf(coef[p], v.w, s.w);
            }
            float4 o;
            o.x = s.x * invL; o.y = s.y * invL; o.z = s.z * invL; o.w = s.w * invL;
            ((float4*)(ACCA + w * EDIM))[e4] = o;
        }
    }
    __syncthreads();

    // out = concat_h[(attn-weighted feat) @ Wv_h] + bv
    {
        int o0 = tid, o1 = tid + 256;
        int h0 = o0 >> 6, h1 = o1 >> 6;
        float a0 = bv[o0], a1 = bv[o1];
        for (int e = 0; e < EDIM; e++) {
            a0 = fmaf(ACCA[h0 * EDIM + e], Wv[(size_t)e * EDIM + o0], a0);
            a1 = fmaf(ACCA[h1 * EDIM + e], Wv[(size_t)e * EDIM + o1], a1);
        }
        OUTS[o0] = a0; OUTS[o1] = a1;
    }
    __syncthreads();

    // proto = out @ Wo + bo
    {
        int o0 = tid, o1 = tid + 256;
        float p0 = bo[o0], p1 = bo[o1];
        for (int e = 0; e < EDIM; e++) {
            float ov = OUTS[e];
            p0 = fmaf(ov, Wo[(size_t)e * EDIM + o0], p0);
            p1 = fmaf(ov, Wo[(size_t)e * EDIM + o1], p1);
        }
        size_t pb = ((size_t)lvl * CCLS + c) * EDIM;
        g_proto[pb + o0] = p0;
        g_proto[pb + o1] = p1;
    }
}

// ---------------- final combine ----------------
__global__ void __launch_bounds__(256) combine_k(const float* __restrict__ lw,
                                                 const float* __restrict__ lt,
                                                 float* __restrict__ out) {
    int idx = blockIdx.x * 256 + threadIdx.x;
    float a0 = lw[0], a1 = lw[1], a2 = lw[2];
    float mx = fmaxf(a0, fmaxf(a1, a2));
    float e0 = expf(a0 - mx), e1 = expf(a1 - mx), e2 = expf(a2 - mx);
    float inv = 1.f / (e0 + e1 + e2);
    float w0 = e0 * inv / lt[0], w1 = e1 * inv / lt[1], w2 = e2 * inv / lt[2];
    out[idx] = g_proto[idx] * w0
             + g_proto[(size_t)CCLS * EDIM + idx] * w1
             + g_proto[(size_t)2 * CCLS * EDIM + idx] * w2;
}

// ---------------- launch ----------------
extern "C" void kernel_launch(void* const* d_in, const int* in_sizes, int n_in,
                              void* d_out, int out_size) {
    (void)in_sizes; (void)n_in; (void)out_size;
    const float* X      = (const float*)d_in[0];
    const int*   labels = (const int*)d_in[1];
    const float* W1     = (const float*)d_in[2];
    const float* b1     = (const float*)d_in[3];
    const float* gamma  = (const float*)d_in[4];
    const float* beta   = (const float*)d_in[5];
    const float* W2     = (const float*)d_in[6];
    const float* b2     = (const float*)d_in[7];
    const float* Wq     = (const float*)d_in[8];
    const float* bq     = (const float*)d_in[9];
    const float* Wk     = (const float*)d_in[10];
    const float* Wv     = (const float*)d_in[12];
    const float* bv     = (const float*)d_in[13];
    const float* Wo     = (const float*)d_in[14];
    const float* bo     = (const float*)d_in[15];
    const float* lw     = (const float*)d_in[16];
    const float* lt     = (const float*)d_in[17];
    float* out = (float*)d_out;

    cudaFuncSetAttribute((const void*)gemm_mma_k<0>, cudaFuncAttributeMaxDynamicSharedMemorySize, GM_SMEM);
    cudaFuncSetAttribute((const void*)gemm_mma_k<1>, cudaFuncAttributeMaxDynamicSharedMemorySize, GM_SMEM);
    cudaFuncSetAttribute((const void*)attn_part_k, cudaFuncAttributeMaxDynamicSharedMemorySize, AP_SMEM);

    __nv_bfloat16 *pxhi, *pxlo, *pahi, *palo, *pwh, *pwl;
    float *pt, *pfeat;
    cudaGetSymbolAddress((void**)&pxhi, g_xhi);
    cudaGetSymbolAddress((void**)&pxlo, g_xlo);
    cudaGetSymbolAddress((void**)&pahi, g_ahi);
    cudaGetSymbolAddress((void**)&palo, g_alo);
    cudaGetSymbolAddress((void**)&pwh, g_wh);
    cudaGetSymbolAddress((void**)&pwl, g_wl);
    cudaGetSymbolAddress((void**)&pt, g_t);
    cudaGetSymbolAddress((void**)&pfeat, g_feat);

    build_k<<<64, 256>>>(labels);
    xsplit_k<<<(NSUP * EDIM / 4) / 256, 256>>>(X);
    wsplit_k<<<dim3(1024, 6), 256>>>(W1, W2);

    // all levels batched per stage
    gemm_mma_k<0><<<dim3(512, 4, LVLS), 256, GM_SMEM>>>(pxhi, pxlo, pwh, pwl, b1, pt);
    ln2_k<<<(LVLS * NSUP) / 256, 256>>>();
    actsplit_k<<<dim3((NSUP * EDIM / 4) / 256, LVLS), 256>>>(gamma, beta);
    gemm_mma_k<1><<<dim3(512, 4, LVLS), 256, GM_SMEM>>>(pahi, palo,
        pwh + (size_t)3 * EDIM * EDIM, pwl + (size_t)3 * EDIM * EDIM, b2, pfeat);
    ctxqu_k<<<dim3(CCLS, LVLS), 512>>>(Wq, bq, Wk);
    attn_part_k<<<dim3(CCLS, NPART, LVLS), 256, AP_SMEM>>>();
    merge_k<<<dim3(CCLS, LVLS), 256>>>(Wv, bv, Wo, bo);
    combine_k<<<128, 256>>>(lw, lt, out);
}

// round 17
// speedup vs baseline: 1.4985x; 1.2310x over previous
#include <cuda_runtime.h>
#include <cuda_fp16.h>
#include <math.h>
#include <stdint.h>

#define NSUP 65536
#define EDIM 512
#define CCLS 64
#define HEADS 8
#define DHEAD 64
#define LVLS 3
#define SLOT 2048
#define NPART 8
#define PLANE_T ((size_t)NSUP * EDIM)
#define PLANE_F ((size_t)CCLS * SLOT * EDIM)

// ---------------- scratch (device globals; no allocation) ----------------
__device__ float g_t[LVLS * PLANE_T];
__device__ float g_feat[LVLS * PLANE_F];
__device__ float g_mu[LVLS * NSUP];
__device__ float g_rstd[LVLS * NSUP];
__device__ int   g_pos[NSUP];
__device__ int   g_count[CCLS];
__device__ float g_proto[(size_t)LVLS * CCLS * EDIM];
__device__ float g_lns[4][LVLS * NSUP];
__device__ float g_lnq[4][LVLS * NSUP];
__device__ float g_ctx[LVLS * CCLS * EDIM];
__device__ float g_uvec[(size_t)LVLS * CCLS * HEADS * EDIM];
__device__ float g_pm[LVLS * CCLS * NPART * HEADS];
__device__ float g_pl[LVLS * CCLS * NPART * HEADS];
__device__ float g_pacc[(size_t)LVLS * CCLS * NPART * HEADS * EDIM];
__device__ __half g_xhi[PLANE_T];
__device__ __half g_xlo[PLANE_T];
__device__ __half g_ahi[LVLS * PLANE_T];
__device__ __half g_alo[LVLS * PLANE_T];
__device__ __half g_wh[(size_t)6 * EDIM * EDIM];   // W^T fp16: [mat][n][k]

// ---------------- PTX helpers ----------------
__device__ __forceinline__ uint32_t smem_u32(const void* p) {
    uint32_t a;
    asm("{ .reg .u64 t; cvta.to.shared.u64 t, %1; cvt.u32.u64 %0, t; }" : "=r"(a) : "l"(p));
    return a;
}
__device__ __forceinline__ void cpa16(uint32_t s, const void* g) {
    asm volatile("cp.async.cg.shared.global [%0], [%1], 16;" :: "r"(s), "l"(g));
}
__device__ __forceinline__ void cpa_commit() { asm volatile("cp.async.commit_group;" ::: "memory"); }
template<int N>
__device__ __forceinline__ void cpa_wait() { asm volatile("cp.async.wait_group %0;" :: "n"(N) : "memory"); }
__device__ __forceinline__ void ldmx4(uint32_t* r, uint32_t a) {
    asm volatile("ldmatrix.sync.aligned.m8n8.x4.shared.b16 {%0,%1,%2,%3}, [%4];"
        : "=r"(r[0]), "=r"(r[1]), "=r"(r[2]), "=r"(r[3]) : "r"(a));
}
__device__ __forceinline__ void mma16816(float* c, const uint32_t* a, uint32_t b0, uint32_t b1) {
    asm volatile("mma.sync.aligned.m16n8k16.row.col.f32.f16.f16.f32 "
        "{%0,%1,%2,%3}, {%4,%5,%6,%7}, {%8,%9}, {%0,%1,%2,%3};"
        : "+f"(c[0]), "+f"(c[1]), "+f"(c[2]), "+f"(c[3])
        : "r"(a[0]), "r"(a[1]), "r"(a[2]), "r"(a[3]), "r"(b0), "r"(b1));
}
__device__ __forceinline__ uint32_t pack2h(__half a, __half b) {
    return (uint32_t)__half_as_ushort(a) | ((uint32_t)__half_as_ushort(b) << 16);
}

// ---------------- build class membership ----------------
__global__ void __launch_bounds__(256) build_k(const int* __restrict__ labels) {
    __shared__ int warp_cnt[8];
    __shared__ int s_base;
    int tid = threadIdx.x, lane = tid & 31, w = tid >> 5;
    int c = blockIdx.x;
    if (tid == 0) s_base = 0;
    __syncthreads();
    for (int base = 0; base < NSUP; base += 256) {
        int n = base + tid;
        bool f = (labels[n] == c);
        unsigned m = __ballot_sync(0xffffffffu, f);
        if (lane == 0) warp_cnt[w] = __popc(m);
        __syncthreads();
        int woff = 0, tot = 0;
        #pragma unroll
        for (int i = 0; i < 8; i++) { int v = warp_cnt[i]; if (i < w) woff += v; tot += v; }
        if (f) g_pos[n] = c * SLOT + s_base + woff + __popc(m & ((1u << lane) - 1u));
        __syncthreads();
        if (tid == 0) s_base += tot;
        __syncthreads();
    }
    if (tid == 0) g_count[c] = s_base;
}

// ---------------- fp16 splits ----------------
__global__ void __launch_bounds__(256) xsplit_k(const float* __restrict__ X) {
    size_t i = (size_t)blockIdx.x * 256 + threadIdx.x;   // float4 index
    float4 v = ((const float4*)X)[i];
    __half h0 = __float2half_rn(v.x), h1 = __float2half_rn(v.y);
    __half h2 = __float2half_rn(v.z), h3 = __float2half_rn(v.w);
    __half l0 = __float2half_rn(v.x - __half2float(h0));
    __half l1 = __float2half_rn(v.y - __half2float(h1));
    __half l2 = __float2half_rn(v.z - __half2float(h2));
    __half l3 = __float2half_rn(v.w - __half2float(h3));
    uint2 ph, pl;
    ph.x = pack2h(h0, h1); ph.y = pack2h(h2, h3);
    pl.x = pack2h(l0, l1); pl.y = pack2h(l2, l3);
    ((uint2*)g_xhi)[i] = ph;
    ((uint2*)g_xlo)[i] = pl;
}

__global__ void __launch_bounds__(256) wsplit_k(const float* __restrict__ W1, const float* __restrict__ W2) {
    int m = blockIdx.y;            // 0..5
    int idx = blockIdx.x * 256 + threadIdx.x;   // < 512*512
    int k = idx >> 9, n = idx & 511;
    const float* src = (m < 3) ? (W1 + (size_t)m * EDIM * EDIM) : (W2 + (size_t)(m - 3) * EDIM * EDIM);
    float v = src[(size_t)k * EDIM + n];
    size_t dst = (size_t)m * EDIM * EDIM + (size_t)n * EDIM + k;   // transpose
    g_wh[dst] = __float2half_rn(v);
}

// ---------------- LN stats from partials (all levels) ----------------
__global__ void __launch_bounds__(256) ln2_k() {
    int row = blockIdx.x * 256 + threadIdx.x;   // < LVLS*NSUP
    float s = g_lns[0][row] + g_lns[1][row] + g_lns[2][row] + g_lns[3][row];
    float q = g_lnq[0][row] + g_lnq[1][row] + g_lnq[2][row] + g_lnq[3][row];
    float mu = s * (1.f / EDIM);
    float var = q * (1.f / EDIM) - mu * mu;
    g_mu[row] = mu;
    g_rstd[row] = rsqrtf(var + 1e-5f);
}

// ---------------- LN + ReLU + fp16 split of activations (per level via blockIdx.y) ----------------
__global__ void __launch_bounds__(256) actsplit_k(const float* __restrict__ gammaL, const float* __restrict__ betaL) {
    int lvl = blockIdx.y;
    size_t i = (size_t)blockIdx.x * 256 + threadIdx.x;   // float4 index within plane
    size_t ip = (size_t)lvl * (PLANE_T / 4) + i;
    float4 v = ((const float4*)g_t)[ip];
    int row = (int)(i >> 7);
    int col = ((int)i & 127) * 4;
    const float* gamma = gammaL + lvl * EDIM;
    const float* beta  = betaL + lvl * EDIM;
    float mu = g_mu[lvl * NSUP + row], rs = g_rstd[lvl * NSUP + row];
    float4 gg = *(const float4*)(gamma + col);
    float4 bb = *(const float4*)(beta + col);
    float a0 = fmaxf(fmaf((v.x - mu) * rs, gg.x, bb.x), 0.f);
    float a1 = fmaxf(fmaf((v.y - mu) * rs, gg.y, bb.y), 0.f);
    float a2 = fmaxf(fmaf((v.z - mu) * rs, gg.z, bb.z), 0.f);
    float a3 = fmaxf(fmaf((v.w - mu) * rs, gg.w, bb.w), 0.f);
    __half h0 = __float2half_rn(a0), h1 = __float2half_rn(a1);
    __half h2 = __float2half_rn(a2), h3 = __float2half_rn(a3);
    __half l0 = __float2half_rn(a0 - __half2float(h0));
    __half l1 = __float2half_rn(a1 - __half2float(h1));
    __half l2 = __float2half_rn(a2 - __half2float(h2));
    __half l3 = __float2half_rn(a3 - __half2float(h3));
    uint2 ph, pl;
    ph.x = pack2h(h0, h1); ph.y = pack2h(h2, h3);
    pl.x = pack2h(l0, l1); pl.y = pack2h(l2, l3);
    ((uint2*)g_ahi)[ip] = ph;
    ((uint2*)g_alo)[ip] = pl;
}

// ---------------- mma.sync GEMM (level-batched via blockIdx.z; fp16 2-pass) ----------------
// C = Ah@Bh + Al@Bh  (B fp16-rounded; A corrected to ~2^-22)
// CTA tile 128x128, 8 warps (2x4), warp tile 64x32, K-chunk 32, cp.async double buffer.
#define GM_NCH 16
#define GM_STRB 80                          // padded row stride in bytes (40 halves)
#define GM_AH 0
#define GM_AL (128 * GM_STRB)               // 10240
#define GM_BH (2 * 128 * GM_STRB)           // 20480
#define GM_BUF (3 * 128 * GM_STRB)          // 30720 per buffer
#define GM_SMEM (2 * GM_BUF)                // 61440 B

template<int EPI>
__global__ void __launch_bounds__(256, 2) gemm_mma_k(
    const __half* __restrict__ Abase, const __half* __restrict__ AbaseLo,
    const __half* __restrict__ WhBase,
    const float* __restrict__ biasBase, float* __restrict__ CoutBase)
{
    extern __shared__ char smem[];
    uint32_t sb = smem_u32(smem);
    int tid = threadIdx.x, lane = tid & 31, wid = tid >> 5;
    int wm = wid >> 2, wn = wid & 3;      // 2 x 4 warp grid; warp tile 64x32
    int row0 = blockIdx.x * 128, col0 = blockIdx.y * 128;
    int z = blockIdx.z;

    const __half* Ahi = Abase   + (EPI == 1 ? (size_t)z * PLANE_T : 0);
    const __half* Alo = AbaseLo + (EPI == 1 ? (size_t)z * PLANE_T : 0);
    const __half* Bhi = WhBase + (size_t)z * EDIM * EDIM;
    const float* bias = biasBase + z * EDIM;
    float* Cout = CoutBase + (size_t)z * (EPI == 0 ? PLANE_T : PLANE_F);

    float acc[4][4][4];                   // [mb][nj][frag]
    #pragma unroll
    for (int i = 0; i < 4; i++)
        #pragma unroll
        for (int j = 0; j < 4; j++)
            #pragma unroll
            for (int t = 0; t < 4; t++) acc[i][j][t] = 0.f;

    int lr = lane & 15, lc = lane >> 4;
    uint32_t a_off = (uint32_t)((wm * 64 + lr) * GM_STRB + lc * 16);
    uint32_t b_off = (uint32_t)(GM_BH + (wn * 32 + lr) * GM_STRB + lc * 16);

    auto load_chunk = [&](int ch) {
        uint32_t s0 = sb + (ch & 1) * GM_BUF;
        int k0 = ch * 32;
        #pragma unroll
        for (int it = 0; it < 2; it++) {
            int u = tid + it * 256;
            int r = u >> 2, sg = u & 3;
            uint32_t so = (uint32_t)(r * GM_STRB + sg * 16);
            size_t ga = (size_t)(row0 + r) * EDIM + k0 + sg * 8;
            size_t gb = (size_t)(col0 + r) * EDIM + k0 + sg * 8;
            cpa16(s0 + GM_AH + so, Ahi + ga);
            cpa16(s0 + GM_AL + so, Alo + ga);
            cpa16(s0 + GM_BH + so, Bhi + gb);
        }
        cpa_commit();
    };

    load_chunk(0);
    load_chunk(1);

    for (int ch = 0; ch < GM_NCH; ch++) {
        if (ch == GM_NCH - 1) cpa_wait<0>(); else cpa_wait<1>();
        __syncthreads();
        uint32_t s0 = sb + (ch & 1) * GM_BUF;
        #pragma unroll
        for (int ks = 0; ks < 2; ks++) {
            uint32_t ah[4][4], al[4][4];
            #pragma unroll
            for (int mb = 0; mb < 4; mb++) {
                uint32_t ra = s0 + a_off + (uint32_t)(mb * 16 * GM_STRB + ks * 32);
                ldmx4(ah[mb], ra);
                ldmx4(al[mb], ra + GM_AL);
            }
            #pragma unroll
            for (int nb = 0; nb < 2; nb++) {
                uint32_t rb = s0 + b_off + (uint32_t)(nb * 16 * GM_STRB + ks * 32);
                uint32_t bh[4];
                ldmx4(bh, rb);
                #pragma unroll
                for (int mb = 0; mb < 4; mb++) {
                    mma16816(acc[mb][nb * 2],     ah[mb], bh[0], bh[2]);
                    mma16816(acc[mb][nb * 2],     al[mb], bh[0], bh[2]);
                    mma16816(acc[mb][nb * 2 + 1], ah[mb], bh[1], bh[3]);
                    mma16816(acc[mb][nb * 2 + 1], al[mb], bh[1], bh[3]);
                }
            }
        }
        __syncthreads();
        if (ch + 2 < GM_NCH) load_chunk(ch + 2);
    }

    // epilogue: bias add; EPI0: dense rows + LN partial sums; EPI1: scatter via g_pos
    float* s_sum = (float*)smem;
    float* s_sq  = (float*)(smem + 2048);
    #pragma unroll
    for (int mb = 0; mb < 4; mb++) {
        int rl = wm * 64 + mb * 16 + (lane >> 2);
        size_t dr0, dr1;
        if (EPI == 0) { dr0 = (size_t)(row0 + rl); dr1 = (size_t)(row0 + rl + 8); }
        else          { dr0 = (size_t)g_pos[row0 + rl]; dr1 = (size_t)g_pos[row0 + rl + 8]; }
        float* d0 = Cout + dr0 * EDIM;
        float* d1 = Cout + dr1 * EDIM;
        float rs0 = 0.f, rq0 = 0.f, rs1 = 0.f, rq1 = 0.f;
        #pragma unroll
        for (int j = 0; j < 4; j++) {
            int col = col0 + wn * 32 + (j >> 1) * 16 + (j & 1) * 8 + (lane & 3) * 2;
            float2 bb = *(const float2*)(bias + col);
            float2 o0, o1;
            o0.x = acc[mb][j][0] + bb.x; o0.y = acc[mb][j][1] + bb.y;
            o1.x = acc[mb][j][2] + bb.x; o1.y = acc[mb][j][3] + bb.y;
            *(float2*)(d0 + col) = o0;
            *(float2*)(d1 + col) = o1;
            if (EPI == 0) {
                rs0 += o0.x + o0.y; rq0 += o0.x * o0.x + o0.y * o0.y;
                rs1 += o1.x + o1.y; rq1 += o1.x * o1.x + o1.y * o1.y;
            }
        }
        if (EPI == 0) {
            rs0 += __shfl_xor_sync(0xffffffffu, rs0, 1); rs0 += __shfl_xor_sync(0xffffffffu, rs0, 2);
            rq0 += __shfl_xor_sync(0xffffffffu, rq0, 1); rq0 += __shfl_xor_sync(0xffffffffu, rq0, 2);
            rs1 += __shfl_xor_sync(0xffffffffu, rs1, 1); rs1 += __shfl_xor_sync(0xffffffffu, rs1, 2);
            rq1 += __shfl_xor_sync(0xffffffffu, rq1, 1); rq1 += __shfl_xor_sync(0xffffffffu, rq1, 2);
            if ((lane & 3) == 0) {
                s_sum[rl * 4 + wn] = rs0;       s_sq[rl * 4 + wn] = rq0;
                s_sum[(rl + 8) * 4 + wn] = rs1; s_sq[(rl + 8) * 4 + wn] = rq1;
            }
        }
    }
    if (EPI == 0) {
        __syncthreads();
        if (tid < 128) {
            float s = s_sum[tid * 4] + s_sum[tid * 4 + 1] + s_sum[tid * 4 + 2] + s_sum[tid * 4 + 3];
            float q = s_sq[tid * 4] + s_sq[tid * 4 + 1] + s_sq[tid * 4 + 2] + s_sq[tid * 4 + 3];
            g_lns[blockIdx.y][z * NSUP + row0 + tid] = s;
            g_lnq[blockIdx.y][z * NSUP + row0 + tid] = q;
        }
    }
}

// ---------------- attention: ctx mean + q + projected u (fused; grid CCLS x LVLS) ----------------
__global__ void __launch_bounds__(512) ctxqu_k(const float* __restrict__ Wq, const float* __restrict__ bq,
                                               const float* __restrict__ Wk) {
    __shared__ float CTX[512];
    __shared__ float Q[512];
    int tid = threadIdx.x;
    int c = blockIdx.x, lvl = blockIdx.y;
    int M = g_count[c];
    const float* fbase = g_feat + (size_t)lvl * PLANE_F + (size_t)c * SLOT * EDIM;

    // ctx: each thread owns one column, coalesced full-row reads
    float s = 0.f;
    #pragma unroll 4
    for (int i = 0; i < M; i++) s += fbase[(size_t)i * EDIM + tid];
    CTX[tid] = s / (float)M;
    __syncthreads();

    // q = ctx @ Wq + bq
    float q = bq[tid];
    for (int k = 0; k < EDIM; k++) q = fmaf(CTX[k], Wq[(size_t)k * EDIM + tid], q);
    Q[tid] = q;
    __syncthreads();

    // u_h = scale * Wk[:, h-block] @ q_h (bk dropped: softmax shift invariance)
    size_t ub = ((size_t)lvl * CCLS + c) * HEADS * EDIM;
    #pragma unroll
    for (int it = 0; it < 8; it++) {
        int idx = tid + it * 512;
        int h = idx >> 9, e = idx & 511;
        const float* wk = Wk + (size_t)e * EDIM + h * DHEAD;
        const float* qh = Q + h * DHEAD;
        float d = 0.f;
        #pragma unroll 8
        for (int dd = 0; dd < DHEAD; dd++) d = fmaf(wk[dd], qh[dd], d);
        g_uvec[ub + idx] = d * 0.125f;
    }
}

// ---------------- attention: partial online softmax (grid CCLS x NPART x LVLS) ----------------
#define AP_SMEM (2 * 8192 * 4)   // FS double buffer = 65536 B

__global__ void __launch_bounds__(256) attn_part_k() {
    extern __shared__ float sm[];
    float* FS = sm;          // 2*16*512

    int tid = threadIdx.x, lane = tid & 31, w = tid >> 5;
    int c = blockIdx.x, p = blockIdx.y, lvl = blockIdx.z;
    int M = g_count[c];
    const float* fbase = g_feat + (size_t)lvl * PLANE_F + (size_t)c * SLOT * EDIM;

    float u4r[16], acc_r[16];
    {
        const float4* U4 = (const float4*)(g_uvec + ((size_t)lvl * CCLS + c) * HEADS * EDIM + w * EDIM);
        #pragma unroll
        for (int q = 0; q < 4; q++) {
            float4 uu = U4[lane + 32 * q];
            u4r[4*q+0] = uu.x; u4r[4*q+1] = uu.y; u4r[4*q+2] = uu.z; u4r[4*q+3] = uu.w;
            acc_r[4*q+0] = 0.f; acc_r[4*q+1] = 0.f; acc_r[4*q+2] = 0.f; acc_r[4*q+3] = 0.f;
        }
    }
    float mmax = -3.0e38f, lsum = 0.f;

    int nch = (M + 15) >> 4;
    auto load_chunk = [&](int ch, int bsel) {
        int rbase = ch * 16;
        #pragma unroll
        for (int jj = 0; jj < 8; jj++) {
            int vid = tid + jj * 256;
            int r = vid >> 7;
            int c4 = vid & 127;
            if (rbase + r < M) {
                float4 v = *(const float4*)(fbase + (size_t)(rbase + r) * EDIM + c4 * 4);
                *(float4*)(FS + bsel * 8192 + r * 512 + c4 * 4) = v;
            }
        }
    };
    if (p < nch) load_chunk(p, 0);
    __syncthreads();
    int it = 0;
    for (int ch = p; ch < nch; ch += NPART, it ^= 1) {
        if (ch + NPART < nch) load_chunk(ch + NPART, it ^ 1);
        int rem = M - ch * 16; if (rem > 16) rem = 16;
        float* fsb = FS + it * 8192;
        float sv[16];
        #pragma unroll
        for (int i = 0; i < 16; i++) {
            if (i < rem) {
                const float4* fr = (const float4*)(fsb + i * 512);
                float d = 0.f;
                #pragma unroll
                for (int q = 0; q < 4; q++) {
                    float4 f = fr[lane + 32 * q];
                    d = fmaf(f.x, u4r[4*q+0], d);
                    d = fmaf(f.y, u4r[4*q+1], d);
                    d = fmaf(f.z, u4r[4*q+2], d);
                    d = fmaf(f.w, u4r[4*q+3], d);
                }
                #pragma unroll
                for (int o = 16; o > 0; o >>= 1) d += __shfl_xor_sync(0xffffffffu, d, o);
                sv[i] = d;
            } else sv[i] = -3.0e38f;
        }
        float m_c = sv[0];
        #pragma unroll
        for (int i = 1; i < 16; i++) m_c = fmaxf(m_c, sv[i]);
        float newmax = fmaxf(mmax, m_c);
        float fac = __expf(mmax - newmax);
        lsum *= fac;
        #pragma unroll
        for (int j = 0; j < 16; j++) acc_r[j] *= fac;
        #pragma unroll
        for (int i = 0; i < 16; i++) {
            if (i < rem) {
                float pex = __expf(sv[i] - newmax);
                lsum += pex;
                const float4* fr = (const float4*)(fsb + i * 512);
                #pragma unroll
                for (int q = 0; q < 4; q++) {
                    float4 f = fr[lane + 32 * q];
                    acc_r[4*q+0] = fmaf(pex, f.x, acc_r[4*q+0]);
                    acc_r[4*q+1] = fmaf(pex, f.y, acc_r[4*q+1]);
                    acc_r[4*q+2] = fmaf(pex, f.z, acc_r[4*q+2]);
                    acc_r[4*q+3] = fmaf(pex, f.w, acc_r[4*q+3]);
                }
            }
        }
        mmax = newmax;
        __syncthreads();
    }
    size_t base = (((size_t)lvl * CCLS + c) * NPART + p) * HEADS + w;
    if (lane == 0) { g_pm[base] = mmax; g_pl[base] = lsum; }
    float4* P4 = (float4*)(g_pacc + base * EDIM);
    #pragma unroll
    for (int q = 0; q < 4; q++) {
        float4 o;
        o.x = acc_r[4*q+0]; o.y = acc_r[4*q+1]; o.z = acc_r[4*q+2]; o.w = acc_r[4*q+3];
        P4[lane + 32 * q] = o;
    }
}

// ---------------- attention: merge partials + Wv + Wo (grid CCLS x LVLS) ----------------
__global__ void __launch_bounds__(256) merge_k(const float* __restrict__ Wv, const float* __restrict__ bv,
                                               const float* __restrict__ Wo, const float* __restrict__ bo) {
    __shared__ float ACCA[HEADS * EDIM];
    __shared__ float OUTS[EDIM];
    int tid = threadIdx.x, lane = tid & 31, w = tid >> 5;
    int c = blockIdx.x, lvl = blockIdx.y;
    size_t cb = ((size_t)lvl * CCLS + c) * NPART;

    // warp w merges head w
    {
        float mp[NPART], lp[NPART];
        float gm = -3.0e38f;
        #pragma unroll
        for (int p = 0; p < NPART; p++) {
            size_t b = (cb + p) * HEADS + w;
            mp[p] = g_pm[b]; lp[p] = g_pl[b];
            gm = fmaxf(gm, mp[p]);
        }
        float coef[NPART];
        float L = 0.f;
        #pragma unroll
        for (int p = 0; p < NPART; p++) { coef[p] = __expf(mp[p] - gm); L += lp[p] * coef[p]; }
        float invL = 1.f / L;
        #pragma unroll
        for (int q = 0; q < 4; q++) {
            int e4 = lane + 32 * q;
            float4 s = make_float4(0.f, 0.f, 0.f, 0.f);
            #pragma unroll
            for (int p = 0; p < NPART; p++) {
                size_t b = (cb + p) * HEADS + w;
                float4 v = ((const float4*)(g_pacc + b * EDIM))[e4];
                s.x = fmaf(coef[p], v.x, s.x); s.y = fmaf(coef[p], v.y, s.y);
                s.z = fmaf(coef[p], v.z, s.z); s.w = fmaf(coef[p], v.w, s.w);
            }
            float4 o;
            o.x = s.x * invL; o.y = s.y * invL; o.z = s.z * invL; o.w = s.w * invL;
            ((float4*)(ACCA + w * EDIM))[e4] = o;
        }
    }
    __syncthreads();

    // out = concat_h[(attn-weighted feat) @ Wv_h] + bv
    {
        int o0 = tid, o1 = tid + 256;
        int h0 = o0 >> 6, h1 = o1 >> 6;
        float a0 = bv[o0], a1 = bv[o1];
        for (int e = 0; e < EDIM; e++) {
            a0 = fmaf(ACCA[h0 * EDIM + e], Wv[(size_t)e * EDIM + o0], a0);
            a1 = fmaf(ACCA[h1 * EDIM + e], Wv[(size_t)e * EDIM + o1], a1);
        }
        OUTS[o0] = a0; OUTS[o1] = a1;
    }
    __syncthreads();

    // proto = out @ Wo + bo
    {
        int o0 = tid, o1 = tid + 256;
        float p0 = bo[o0], p1 = bo[o1];
        for (int e = 0; e < EDIM; e++) {
            float ov = OUTS[e];
            p0 = fmaf(ov, Wo[(size_t)e * EDIM + o0], p0);
            p1 = fmaf(ov, Wo[(size_t)e * EDIM + o1], p1);
        }
        size_t pb = ((size_t)lvl * CCLS + c) * EDIM;
        g_proto[pb + o0] = p0;
        g_proto[pb + o1] = p1;
    }
}

// ---------------- final combine ----------------
__global__ void __launch_bounds__(256) combine_k(const float* __restrict__ lw,
                                                 const float* __restrict__ lt,
                                                 float* __restrict__ out) {
    int idx = blockIdx.x * 256 + threadIdx.x;
    float a0 = lw[0], a1 = lw[1], a2 = lw[2];
    float mx = fmaxf(a0, fmaxf(a1, a2));
    float e0 = expf(a0 - mx), e1 = expf(a1 - mx), e2 = expf(a2 - mx);
    float inv = 1.f / (e0 + e1 + e2);
    float w0 = e0 * inv / lt[0], w1 = e1 * inv / lt[1], w2 = e2 * inv / lt[2];
    out[idx] = g_proto[idx] * w0
             + g_proto[(size_t)CCLS * EDIM + idx] * w1
             + g_proto[(size_t)2 * CCLS * EDIM + idx] * w2;
}

// ---------------- launch ----------------
extern "C" void kernel_launch(void* const* d_in, const int* in_sizes, int n_in,
                              void* d_out, int out_size) {
    (void)in_sizes; (void)n_in; (void)out_size;
    const float* X      = (const float*)d_in[0];
    const int*   labels = (const int*)d_in[1];
    const float* W1     = (const float*)d_in[2];
    const float* b1     = (const float*)d_in[3];
    const float* gamma  = (const float*)d_in[4];
    const float* beta   = (const float*)d_in[5];
    const float* W2     = (const float*)d_in[6];
    const float* b2     = (const float*)d_in[7];
    const float* Wq     = (const float*)d_in[8];
    const float* bq     = (const float*)d_in[9];
    const float* Wk     = (const float*)d_in[10];
    const float* Wv     = (const float*)d_in[12];
    const float* bv     = (const float*)d_in[13];
    const float* Wo     = (const float*)d_in[14];
    const float* bo     = (const float*)d_in[15];
    const float* lw     = (const float*)d_in[16];
    const float* lt     = (const float*)d_in[17];
    float* out = (float*)d_out;

    cudaFuncSetAttribute((const void*)gemm_mma_k<0>, cudaFuncAttributeMaxDynamicSharedMemorySize, GM_SMEM);
    cudaFuncSetAttribute((const void*)gemm_mma_k<1>, cudaFuncAttributeMaxDynamicSharedMemorySize, GM_SMEM);
    cudaFuncSetAttribute((const void*)attn_part_k, cudaFuncAttributeMaxDynamicSharedMemorySize, AP_SMEM);

    __half *pxhi, *pxlo, *pahi, *palo, *pwh;
    float *pt, *pfeat;
    cudaGetSymbolAddress((void**)&pxhi, g_xhi);
    cudaGetSymbolAddress((void**)&pxlo, g_xlo);
    cudaGetSymbolAddress((void**)&pahi, g_ahi);
    cudaGetSymbolAddress((void**)&palo, g_alo);
    cudaGetSymbolAddress((void**)&pwh, g_wh);
    cudaGetSymbolAddress((void**)&pt, g_t);
    cudaGetSymbolAddress((void**)&pfeat, g_feat);

    build_k<<<64, 256>>>(labels);
    xsplit_k<<<(NSUP * EDIM / 4) / 256, 256>>>(X);
    wsplit_k<<<dim3(1024, 6), 256>>>(W1, W2);

    // all levels batched per stage
    gemm_mma_k<0><<<dim3(512, 4, LVLS), 256, GM_SMEM>>>(pxhi, pxlo, pwh, b1, pt);
    ln2_k<<<(LVLS * NSUP) / 256, 256>>>();
    actsplit_k<<<dim3((NSUP * EDIM / 4) / 256, LVLS), 256>>>(gamma, beta);
    gemm_mma_k<1><<<dim3(512, 4, LVLS), 256, GM_SMEM>>>(pahi, palo,
        pwh + (size_t)3 * EDIM * EDIM, b2, pfeat);
    ctxqu_k<<<dim3(CCLS, LVLS), 512>>>(Wq, bq, Wk);
    attn_part_k<<<dim3(CCLS, NPART, LVLS), 256, AP_SMEM>>>();
    merge_k<<<dim3(CCLS, LVLS), 256>>>(Wv, bv, Wo, bo);
    combine_k<<<128, 256>>>(lw, lt, out);
}